// round 12
// baseline (speedup 1.0000x reference)
#include <cuda_runtime.h>
#include <math.h>
#include <stdint.h>

// Problem constants
#define T_SEQ 384
#define N_NEU 128
#define D_MOD 512
#define H_HEADS 8
#define DHEAD 64
#define M_ROWS (N_NEU * T_SEQ)   // 49152
#define QKV_ELEMS (N_NEU * H_HEADS * T_SEQ * DHEAD)  // 25165824
#define WSZ (D_MOD * D_MOD)      // 262144

// Q pre-scale: (1/sqrt(64)) * log2(e) so softmax can use raw exp2
#define QSCALE 0.18033688011112042f

// Scratch (device globals).
// g_XNt, g_Wt, g_Yt are stored K-PERMUTED: within each 32-element block of
// the K (input-feature) dimension, element k = ks*8 + half*4 + qk lives at
// position qk*8 + ks*2 + half. This makes mma fragment pairs adjacent.
__device__ uint32_t g_XNt[N_NEU * T_SEQ * D_MOD];  // tf32 bits, k-permuted
__device__ uint32_t g_Q[QKV_ELEMS];                // tf32 bits, normal layout
__device__ uint32_t g_K[QKV_ELEMS];                // tf32 bits, normal layout
__device__ uint32_t g_V[QKV_ELEMS];                // tf32 bits, normal layout
__device__ uint32_t g_Yt[M_ROWS * D_MOD];          // tf32 bits, k-permuted
__device__ uint32_t g_Wt[4 * WSZ];                 // tf32 weights, k-permuted

// ---------------------------------------------------------------------------
// helpers
// ---------------------------------------------------------------------------
__device__ __forceinline__ int permk(int k) {
    // within-32-block permutation; block base preserved
    return (k & ~31) | ((k & 3) << 3) | (((k >> 3) & 3) << 1) | ((k >> 2) & 1);
}

__device__ __forceinline__ uint32_t f2tf32(float f) {
    uint32_t r;
    asm("cvt.rna.tf32.f32 %0, %1;" : "=r"(r) : "f"(f));
    return r;
}

__device__ __forceinline__ void mma_tf32(float c[4], const uint32_t a[4],
                                         const uint32_t b[2]) {
    asm volatile(
        "mma.sync.aligned.m16n8k8.row.col.f32.tf32.tf32.f32 "
        "{%0,%1,%2,%3}, {%4,%5,%6,%7}, {%8,%9}, {%0,%1,%2,%3};"
        : "+f"(c[0]), "+f"(c[1]), "+f"(c[2]), "+f"(c[3])
        : "r"(a[0]), "r"(a[1]), "r"(a[2]), "r"(a[3]),
          "r"(b[0]), "r"(b[1]));
}

__device__ __forceinline__ uint32_t smem_u32(const void* p) {
    return (uint32_t)__cvta_generic_to_shared(p);
}
#define CP_ASYNC16(dst, src) \
    asm volatile("cp.async.cg.shared.global [%0], [%1], 16;" \
                 :: "r"(dst), "l"(src))
#define CP_ASYNC8(dst, src) \
    asm volatile("cp.async.ca.shared.global [%0], [%1], 8;" \
                 :: "r"(dst), "l"(src))
#define CP_COMMIT() asm volatile("cp.async.commit_group;" ::: "memory")
#define CP_WAIT0()  asm volatile("cp.async.wait_group 0;" ::: "memory")

// ---------------------------------------------------------------------------
// Kernel 0: weight -> tf32 conversion, k-permuted store
// ---------------------------------------------------------------------------
__global__ void wcvt_kernel(const float* __restrict__ wq,
                            const float* __restrict__ wk,
                            const float* __restrict__ wv,
                            const float* __restrict__ wo) {
    int i = blockIdx.x * 256 + threadIdx.x;
    int w = blockIdx.y;
    const float* src = (w == 0) ? wq : (w == 1) ? wk : (w == 2) ? wv : wo;
    g_Wt[w * WSZ + (i & ~511) + permk(i & 511)] = f2tf32(src[i]);
}

// ---------------------------------------------------------------------------
// Kernel 1: RMSNorm + transpose (t,n,d) -> (n,t,d); tf32, k-permuted store
// ---------------------------------------------------------------------------
__global__ void rmsnorm_kernel(const float* __restrict__ x,
                               const float* __restrict__ w) {
    int row = blockIdx.x;          // row = t*128 + n
    int t = row >> 7;
    int n = row & 127;
    int tid = threadIdx.x;

    float4 v = ((const float4*)(x + (size_t)row * D_MOD))[tid];
    float ss = v.x * v.x + v.y * v.y + v.z * v.z + v.w * v.w;
    #pragma unroll
    for (int m = 16; m; m >>= 1) ss += __shfl_xor_sync(0xffffffffu, ss, m);

    __shared__ float sbuf[4];
    if ((tid & 31) == 0) sbuf[tid >> 5] = ss;
    __syncthreads();
    float tot = sbuf[0] + sbuf[1] + sbuf[2] + sbuf[3];
    float inv = rsqrtf(tot * (1.0f / (float)D_MOD) + 1e-6f);

    float4 wv = ((const float4*)w)[tid];
    uint32_t* dst = g_XNt + ((size_t)n * T_SEQ + t) * D_MOD;
    int k0 = 4 * tid;
    dst[permk(k0 + 0)] = f2tf32(v.x * inv * wv.x);
    dst[permk(k0 + 1)] = f2tf32(v.y * inv * wv.y);
    dst[permk(k0 + 2)] = f2tf32(v.z * inv * wv.z);
    dst[permk(k0 + 3)] = f2tf32(v.w * inv * wv.w);
}

// ---------------------------------------------------------------------------
// GEMM mainloop: C(128x128) = A(128xK) * B(128xK)^T, K=512, tf32 bits in,
// A/B k-permuted in gmem. 128 threads, 4 warps, warp tile 64x64.
// 2-stage pipeline with 8-byte cp.async (stride 34 words: dst is 8B-aligned;
// 16B alignment is impossible with an LDS.64-optimal stride).
// Fragment loads are LDS.64 (pairs adjacent via k-permutation); stride 34
// gives optimal 2-way pair-bank spread. smem 69632 B -> 3 CTAs/SM.
// ---------------------------------------------------------------------------
#define SMS 34
#define GEMM_STAGE_U (2 * 128 * SMS)            // 8704 words per stage (A+B)
#define GEMM_SMEM_BYTES (2 * GEMM_STAGE_U * 4)  // 69632 B

__device__ __forceinline__ void gemm_mainloop_tf32(
    const uint32_t* __restrict__ A, const uint32_t* __restrict__ B,
    int m0, int n0row, uint32_t* __restrict__ sm,
    float c[4][8][4], int tid)
{
    const int lane = tid & 31;
    const int warp = tid >> 5;      // 0..3
    const int wm = warp & 1;
    const int wn = warp >> 1;
    const int group = lane >> 2;
    const int qk = lane & 3;
    const int q8 = qk * 8;

    const uint32_t smb = smem_u32(sm);
    const int crow0 = tid >> 4;         // 0..7 (+8*i)
    const int cu2 = (tid & 15) << 1;    // word offset of 8B unit: 0,2,...,30

    // prologue: chunk 0 -> stage 0
    #pragma unroll
    for (int i = 0; i < 16; i++) {
        int row = crow0 + i * 8;
        CP_ASYNC8(smb + (uint32_t)(row * SMS + cu2) * 4,
                  A + (size_t)(m0 + row) * 512 + cu2);
        CP_ASYNC8(smb + (uint32_t)(128 * SMS + row * SMS + cu2) * 4,
                  B + (size_t)(n0row + row) * 512 + cu2);
    }
    CP_COMMIT();

    for (int kb = 0; kb < 16; kb++) {
        CP_WAIT0();
        __syncthreads();          // chunk kb visible; stage[(kb+1)&1] free

        const uint32_t* As = sm + (kb & 1) * GEMM_STAGE_U;
        const uint32_t* Bs = As + 128 * SMS;

        if (kb + 1 < 16) {
            uint32_t st = smb + (uint32_t)(((kb + 1) & 1) * GEMM_STAGE_U) * 4;
            int kc = (kb + 1) * 32;
            #pragma unroll
            for (int i = 0; i < 16; i++) {
                int row = crow0 + i * 8;
                CP_ASYNC8(st + (uint32_t)(row * SMS + cu2) * 4,
                          A + (size_t)(m0 + row) * 512 + kc + cu2);
                CP_ASYNC8(st + (uint32_t)(128 * SMS + row * SMS + cu2) * 4,
                          B + (size_t)(n0row + row) * 512 + kc + cu2);
            }
            CP_COMMIT();
        }

        #pragma unroll
        for (int ks = 0; ks < 4; ks++) {
            const int kp = q8 + ks * 2;   // permuted position of (k0+qk, k0+4+qk)
            uint32_t af[4][4];
            #pragma unroll
            for (int mt = 0; mt < 4; mt++) {
                int r0 = wm * 64 + mt * 16;
                uint2 lo = *(const uint2*)&As[(r0 + group) * SMS + kp];
                uint2 hi = *(const uint2*)&As[(r0 + 8 + group) * SMS + kp];
                af[mt][0] = lo.x; af[mt][1] = hi.x;
                af[mt][2] = lo.y; af[mt][3] = hi.y;
            }
            #pragma unroll
            for (int nt = 0; nt < 8; nt++) {
                int nr = wn * 64 + nt * 8;
                uint2 bv = *(const uint2*)&Bs[(nr + group) * SMS + kp];
                uint32_t bf[2] = { bv.x, bv.y };
                #pragma unroll
                for (int mt = 0; mt < 4; mt++)
                    mma_tf32(c[mt][nt], af[mt], bf);
            }
        }
    }
}

// ---------------------------------------------------------------------------
// Kernel 2: QKV projection (tf32 TC) with FUSED RoPE + q-scale epilogue.
// Q/K/V written in NORMAL layout (attention consumes them directly).
// ---------------------------------------------------------------------------
__global__ void __launch_bounds__(128, 3)
qkv_gemm_tc_kernel() {
    extern __shared__ uint32_t dynsm_u[];

    int n0 = blockIdx.x * 128;
    int m0 = blockIdx.y * 128;
    int which = n0 >> 9;                 // 0=Q, 1=K, 2=V
    int cc0 = n0 & 511;
    uint32_t* Dst = (which == 0) ? g_Q : ((which == 1) ? g_K : g_V);

    int tid = threadIdx.x;
    float c[4][8][4] = {};
    gemm_mainloop_tf32(g_XNt, g_Wt + (size_t)which * WSZ, m0, cc0, dynsm_u, c, tid);

    const int lane = tid & 31;
    const int warp = tid >> 5;
    const int wm = warp & 1, wn = warp >> 1;
    const int group = lane >> 2, qk = lane & 3;

    #pragma unroll
    for (int mt = 0; mt < 4; mt++) {
        #pragma unroll
        for (int half = 0; half < 2; half++) {
            int m = m0 + wm * 64 + mt * 16 + group + half * 8;
            int r = m / T_SEQ;
            int t = m - r * T_SEQ;
            #pragma unroll
            for (int nt = 0; nt < 8; nt++) {
                int col = wn * 64 + nt * 8 + qk * 2;
                int cc = cc0 + col;
                int h = cc >> 6, dh = cc & 63;
                float vx = c[mt][nt][half * 2 + 0];
                float vy = c[mt][nt][half * 2 + 1];
                if (which <= 1 && dh < 32) {
                    int i = dh >> 1;
                    float invf = __expf(-(float)i * 0.57564627324851142f);
                    float sn, cs;
                    sincosf((float)t * invf, &sn, &cs);
                    float a = vx, b = vy;
                    vx = a * cs - b * sn;
                    vy = a * sn + b * cs;
                }
                if (which == 0) { vx *= QSCALE; vy *= QSCALE; }
                uint2 uv = make_uint2(f2tf32(vx), f2tf32(vy));
                *(uint2*)(Dst + (((size_t)(r * H_HEADS + h) * T_SEQ) + t) * DHEAD + dh) = uv;
            }
        }
    }
}

// ---------------------------------------------------------------------------
// Kernel 3: tensor-core causal flash attention.
// q-tile 64, 128 threads. 2-stage cp.async KV ring; Q staged through the
// stage-1 buffer then hoisted to registers. Softmax in exp2 domain.
// P transposed C->A via intra-quad shuffles. Epilogue writes g_Yt K-PERMUTED
// and reads the g_XNt residual K-PERMUTED.
// ---------------------------------------------------------------------------
#define ATT_STR 68
#define ATT_KV_W (2 * 64 * ATT_STR)             // 8704 words per stage (K+V)
#define ATT_SMEM_WORDS (2 * ATT_KV_W)           // 69632 B

__global__ void __launch_bounds__(128, 3)
attn_tc_kernel(const int* __restrict__ pad_mask) {
    extern __shared__ uint32_t smu[];

    const int qt = blockIdx.x;           // 0..5
    const int rh = blockIdx.y;
    const int r = rh >> 3, h = rh & 7;
    const int qbase = qt * 64;

    const int tid = threadIdx.x;
    const int warp = tid >> 5;           // 0..3
    const int lane = tid & 31;
    const int g = lane >> 2;
    const int qk = lane & 3;
    const int wrow = warp * 16;
    const int src1 = (lane & ~3) | (qk >> 1);
    const int src2 = src1 + 2;
    const bool oddqk = (qk & 1);

    const uint32_t smb = smem_u32(smu);
    const int ntiles = qt + 1;

    // prologue: kv tile 0 -> stage 0
    {
        const uint32_t* Kp = g_K + ((size_t)rh * T_SEQ) * DHEAD;
        const uint32_t* Vp = g_V + ((size_t)rh * T_SEQ) * DHEAD;
        #pragma unroll
        for (int i = 0; i < 8; i++) {
            int idx = tid + i * 128;
            int row = idx >> 4, c4 = (idx & 15) << 2;
            CP_ASYNC16(smb + (uint32_t)(row * ATT_STR + c4) * 4,
                       Kp + row * DHEAD + c4);
            CP_ASYNC16(smb + (uint32_t)(64 * ATT_STR + row * ATT_STR + c4) * 4,
                       Vp + row * DHEAD + c4);
        }
        CP_COMMIT();
    }

    // stage Q (64x64) through the stage-1 K region, hoist to registers.
    {
        uint32_t* Qst = smu + ATT_KV_W;
        const uint32_t* Qp = g_Q + ((size_t)rh * T_SEQ + qbase) * DHEAD;
        #pragma unroll
        for (int i = 0; i < 8; i++) {
            int idx = tid + i * 128;
            int row = idx >> 4, c4 = (idx & 15) << 2;
            *(uint4*)(Qst + row * ATT_STR + c4) = *(const uint4*)(Qp + row * DHEAD + c4);
        }
    }
    __syncthreads();

    uint32_t qf[8][4];
    {
        const uint32_t* Qst = smu + ATT_KV_W;
        #pragma unroll
        for (int ks8 = 0; ks8 < 8; ks8++) {
            int k0 = ks8 * 8;
            qf[ks8][0] = Qst[(wrow + g) * ATT_STR + k0 + qk];
            qf[ks8][1] = Qst[(wrow + 8 + g) * ATT_STR + k0 + qk];
            qf[ks8][2] = Qst[(wrow + g) * ATT_STR + k0 + 4 + qk];
            qf[ks8][3] = Qst[(wrow + 8 + g) * ATT_STR + k0 + 4 + qk];
        }
    }

    float o[8][4] = {};
    float m0r = -1e30f, m1r = -1e30f;
    float l0r = 0.f, l1r = 0.f;

    for (int kt = 0; kt < ntiles; kt++) {
        const int kbase = kt * 64;
        CP_WAIT0();
        __syncthreads();

        if (kt + 1 < ntiles) {
            const uint32_t* Kp = g_K + ((size_t)rh * T_SEQ + (kt + 1) * 64) * DHEAD;
            const uint32_t* Vp = g_V + ((size_t)rh * T_SEQ + (kt + 1) * 64) * DHEAD;
            uint32_t sb = smb + (uint32_t)(((kt + 1) & 1) * ATT_KV_W) * 4;
            #pragma unroll
            for (int i = 0; i < 8; i++) {
                int idx = tid + i * 128;
                int row = idx >> 4, c4 = (idx & 15) << 2;
                CP_ASYNC16(sb + (uint32_t)(row * ATT_STR + c4) * 4,
                           Kp + row * DHEAD + c4);
                CP_ASYNC16(sb + (uint32_t)(64 * ATT_STR + row * ATT_STR + c4) * 4,
                           Vp + row * DHEAD + c4);
            }
            CP_COMMIT();
        }

        const uint32_t* Ks = smu + (kt & 1) * ATT_KV_W;
        const uint32_t* Vs = Ks + 64 * ATT_STR;

        // ---- S = Q K^T (scores in log2 domain via Q pre-scale) ----
        float s[8][4] = {};
        #pragma unroll
        for (int ks8 = 0; ks8 < 8; ks8++) {
            int k0 = ks8 * 8;
            #pragma unroll
            for (int nt = 0; nt < 8; nt++) {
                uint32_t bf[2];
                bf[0] = Ks[(nt * 8 + g) * ATT_STR + k0 + qk];
                bf[1] = Ks[(nt * 8 + g) * ATT_STR + k0 + 4 + qk];
                mma_tf32(s[nt], qf[ks8], bf);
            }
        }

        const int row0 = qbase + wrow + g;
        const int row1 = row0 + 8;

        // ---- causal mask (only the diagonal tile) ----
        if (kt == qt) {
            #pragma unroll
            for (int nt = 0; nt < 8; nt++) {
                int c0 = kbase + nt * 8 + 2 * qk;
                if (c0 > row0)     s[nt][0] = -1e30f;
                if (c0 + 1 > row0) s[nt][1] = -1e30f;
                if (c0 > row1)     s[nt][2] = -1e30f;
                if (c0 + 1 > row1) s[nt][3] = -1e30f;
            }
        }

        // ---- online softmax (exp2 domain) ----
        float tmax0 = -1e30f, tmax1 = -1e30f;
        #pragma unroll
        for (int nt = 0; nt < 8; nt++) {
            tmax0 = fmaxf(tmax0, fmaxf(s[nt][0], s[nt][1]));
            tmax1 = fmaxf(tmax1, fmaxf(s[nt][2], s[nt][3]));
        }
        tmax0 = fmaxf(tmax0, __shfl_xor_sync(0xffffffffu, tmax0, 1));
        tmax0 = fmaxf(tmax0, __shfl_xor_sync(0xffffffffu, tmax0, 2));
        tmax1 = fmaxf(tmax1, __shfl_xor_sync(0xffffffffu, tmax1, 1));
        tmax1 = fmaxf(tmax1, __shfl_xor_sync(0xffffffffu, tmax1, 2));

        float nm0 = fmaxf(m0r, tmax0), nm1 = fmaxf(m1r, tmax1);
        float scl0 = exp2f(m0r - nm0), scl1 = exp2f(m1r - nm1);
        float ts0 = 0.f, ts1 = 0.f;
        #pragma unroll
        for (int nt = 0; nt < 8; nt++) {
            s[nt][0] = exp2f(s[nt][0] - nm0);
            s[nt][1] = exp2f(s[nt][1] - nm0);
            s[nt][2] = exp2f(s[nt][2] - nm1);
            s[nt][3] = exp2f(s[nt][3] - nm1);
            ts0 += s[nt][0] + s[nt][1];
            ts1 += s[nt][2] + s[nt][3];
        }
        ts0 += __shfl_xor_sync(0xffffffffu, ts0, 1);
        ts0 += __shfl_xor_sync(0xffffffffu, ts0, 2);
        ts1 += __shfl_xor_sync(0xffffffffu, ts1, 1);
        ts1 += __shfl_xor_sync(0xffffffffu, ts1, 2);
        l0r = l0r * scl0 + ts0;
        l1r = l1r * scl1 + ts1;
        m0r = nm0; m1r = nm1;
        #pragma unroll
        for (int nt = 0; nt < 8; nt++) {
            o[nt][0] *= scl0; o[nt][1] *= scl0;
            o[nt][2] *= scl1; o[nt][3] *= scl1;
        }

        // ---- O += P @ V (P transposed C->A via intra-quad shuffles) ----
        #pragma unroll
        for (int nt = 0; nt < 8; nt++) {
            float b0 = __shfl_sync(0xffffffffu, s[nt][0], src1);
            float b1 = __shfl_sync(0xffffffffu, s[nt][1], src1);
            float b2 = __shfl_sync(0xffffffffu, s[nt][2], src1);
            float b3 = __shfl_sync(0xffffffffu, s[nt][3], src1);
            float d0 = __shfl_sync(0xffffffffu, s[nt][0], src2);
            float d1 = __shfl_sync(0xffffffffu, s[nt][1], src2);
            float d2 = __shfl_sync(0xffffffffu, s[nt][2], src2);
            float d3 = __shfl_sync(0xffffffffu, s[nt][3], src2);
            uint32_t af[4];
            af[0] = f2tf32(oddqk ? b1 : b0);
            af[1] = f2tf32(oddqk ? b3 : b2);
            af[2] = f2tf32(oddqk ? d1 : d0);
            af[3] = f2tf32(oddqk ? d3 : d2);
            int k0 = nt * 8;
            #pragma unroll
            for (int ot = 0; ot < 8; ot++) {
                uint32_t bf[2];
                bf[0] = Vs[(k0 + qk) * ATT_STR + ot * 8 + g];
                bf[1] = Vs[(k0 + 4 + qk) * ATT_STR + ot * 8 + g];
                mma_tf32(o[ot], af, bf);
            }
        }
    }

    // ---- epilogue: normalize, pad mask, residual, k-permuted Yt store ----
    const bool valid = (pad_mask[r] != 0);
    const float inv0 = 1.0f / l0r, inv1 = 1.0f / l1r;
    const int t0 = qbase + wrow + g;
    const int t1 = t0 + 8;
    #pragma unroll
    for (int nt = 0; nt < 8; nt++) {
        int kk = h * DHEAD + nt * 8 + 2 * qk;    // K-dim index of out-proj
        int p0 = permk(kk), p1 = permk(kk + 1);

        const uint32_t* xb0 = g_XNt + ((size_t)r * T_SEQ + t0) * D_MOD;
        uint32_t* yb0 = g_Yt + ((size_t)t0 * N_NEU + r) * D_MOD;
        float ox0 = (valid ? o[nt][0] * inv0 : 0.f) + __uint_as_float(xb0[p0]);
        float oy0 = (valid ? o[nt][1] * inv0 : 0.f) + __uint_as_float(xb0[p1]);
        yb0[p0] = f2tf32(ox0);
        yb0[p1] = f2tf32(oy0);

        const uint32_t* xb1 = g_XNt + ((size_t)r * T_SEQ + t1) * D_MOD;
        uint32_t* yb1 = g_Yt + ((size_t)t1 * N_NEU + r) * D_MOD;
        float ox1 = (valid ? o[nt][2] * inv1 : 0.f) + __uint_as_float(xb1[p0]);
        float oy1 = (valid ? o[nt][3] * inv1 : 0.f) + __uint_as_float(xb1[p1]);
        yb1[p0] = f2tf32(ox1);
        yb1[p1] = f2tf32(oy1);
    }
}

// ---------------------------------------------------------------------------
// Kernel 4: output projection (tf32 TC, 2-stage cp.async, 3 CTAs/SM).
// Output written in NORMAL layout (only the K dim is permuted, in inputs).
// ---------------------------------------------------------------------------
__global__ void __launch_bounds__(128, 3)
out_gemm_tc_kernel(float* __restrict__ out) {
    extern __shared__ uint32_t dynsm_u[];

    int n0 = blockIdx.x * 128;
    int m0 = blockIdx.y * 128;
    int tid = threadIdx.x;

    float c[4][8][4] = {};
    gemm_mainloop_tf32(g_Yt, g_Wt + (size_t)3 * WSZ, m0, n0, dynsm_u, c, tid);

    const int lane = tid & 31;
    const int warp = tid >> 5;
    const int wm = warp & 1, wn = warp >> 1;
    const int group = lane >> 2, qk = lane & 3;

    #pragma unroll
    for (int mt = 0; mt < 4; mt++) {
        #pragma unroll
        for (int half = 0; half < 2; half++) {
            int m = m0 + wm * 64 + mt * 16 + group + half * 8;
            #pragma unroll
            for (int nt = 0; nt < 8; nt++) {
                int col = n0 + wn * 64 + nt * 8 + qk * 2;
                float2 v;
                v.x = c[mt][nt][half * 2 + 0];
                v.y = c[mt][nt][half * 2 + 1];
                *(float2*)(out + (size_t)m * 512 + col) = v;
            }
        }
    }
}

// ---------------------------------------------------------------------------
extern "C" void kernel_launch(void* const* d_in, const int* in_sizes, int n_in,
                              void* d_out, int out_size) {
    const float* x       = (const float*)d_in[0];
    const int*   pad     = (const int*)d_in[1];
    const float* norm_w  = (const float*)d_in[2];
    const float* wq      = (const float*)d_in[3];
    const float* wk      = (const float*)d_in[4];
    const float* wv      = (const float*)d_in[5];
    const float* wo      = (const float*)d_in[6];
    float* out = (float*)d_out;
    (void)in_sizes; (void)n_in; (void)out_size;

    cudaFuncSetAttribute(attn_tc_kernel,
                         cudaFuncAttributeMaxDynamicSharedMemorySize,
                         ATT_SMEM_WORDS * 4);
    cudaFuncSetAttribute(qkv_gemm_tc_kernel,
                         cudaFuncAttributeMaxDynamicSharedMemorySize,
                         GEMM_SMEM_BYTES);
    cudaFuncSetAttribute(out_gemm_tc_kernel,
                         cudaFuncAttributeMaxDynamicSharedMemorySize,
                         GEMM_SMEM_BYTES);

    // 0. weights -> tf32 (k-permuted)
    wcvt_kernel<<<dim3(WSZ / 256, 4), 256>>>(wq, wk, wv, wo);

    // 1. RMSNorm + transpose (tf32, k-permuted)
    rmsnorm_kernel<<<M_ROWS, 128>>>(x, norm_w);

    // 2. QKV projection (tf32 TC, LDS.64 fragments) + fused RoPE
    qkv_gemm_tc_kernel<<<dim3(1536 / 128, M_ROWS / 128), 128,
                         GEMM_SMEM_BYTES>>>();

    // 3. tensor-core causal attention (q-tile 64, 3 CTAs/SM)
    attn_tc_kernel<<<dim3(T_SEQ / 64, N_NEU * H_HEADS), 128,
                     ATT_SMEM_WORDS * 4>>>(pad);

    // 4. output projection (tf32 TC, LDS.64 fragments)
    out_gemm_tc_kernel<<<dim3(512 / 128, M_ROWS / 128), 128,
                         GEMM_SMEM_BYTES>>>(out);
}

// round 13
// speedup vs baseline: 1.3098x; 1.3098x over previous
#include <cuda_runtime.h>
#include <math.h>
#include <stdint.h>

// Problem constants
#define T_SEQ 384
#define N_NEU 128
#define D_MOD 512
#define H_HEADS 8
#define DHEAD 64
#define M_ROWS (N_NEU * T_SEQ)   // 49152
#define QKV_ELEMS (N_NEU * H_HEADS * T_SEQ * DHEAD)  // 25165824
#define WSZ (D_MOD * D_MOD)      // 262144

// Q pre-scale: (1/sqrt(64)) * log2(e) so softmax can use raw exp2
#define QSCALE 0.18033688011112042f

// Scratch (device globals) — all linear layouts (k-permute reverted).
__device__ uint32_t g_XNt[N_NEU * T_SEQ * D_MOD];  // tf32 bits (also residual)
__device__ uint32_t g_Q[QKV_ELEMS];                // tf32 bits, rope+scale applied
__device__ uint32_t g_K[QKV_ELEMS];                // tf32 bits, rope applied
__device__ uint32_t g_V[QKV_ELEMS];                // tf32 bits
__device__ uint32_t g_Yt[M_ROWS * D_MOD];          // tf32 bits, (t*128+n, d)
__device__ uint32_t g_Wt[4 * WSZ];                 // tf32 weights: wq,wk,wv,wo

// ---------------------------------------------------------------------------
// helpers
// ---------------------------------------------------------------------------
__device__ __forceinline__ uint32_t f2tf32(float f) {
    uint32_t r;
    asm("cvt.rna.tf32.f32 %0, %1;" : "=r"(r) : "f"(f));
    return r;
}

__device__ __forceinline__ void mma_tf32(float c[4], const uint32_t a[4],
                                         const uint32_t b[2]) {
    asm volatile(
        "mma.sync.aligned.m16n8k8.row.col.f32.tf32.tf32.f32 "
        "{%0,%1,%2,%3}, {%4,%5,%6,%7}, {%8,%9}, {%0,%1,%2,%3};"
        : "+f"(c[0]), "+f"(c[1]), "+f"(c[2]), "+f"(c[3])
        : "r"(a[0]), "r"(a[1]), "r"(a[2]), "r"(a[3]),
          "r"(b[0]), "r"(b[1]));
}

__device__ __forceinline__ uint32_t smem_u32(const void* p) {
    return (uint32_t)__cvta_generic_to_shared(p);
}
#define CP_ASYNC16(dst, src) \
    asm volatile("cp.async.cg.shared.global [%0], [%1], 16;" \
                 :: "r"(dst), "l"(src))
#define CP_COMMIT() asm volatile("cp.async.commit_group;" ::: "memory")
#define CP_WAIT0()  asm volatile("cp.async.wait_group 0;" ::: "memory")

// ---------------------------------------------------------------------------
// Kernel 0: weight -> tf32 conversion
// ---------------------------------------------------------------------------
__global__ void wcvt_kernel(const float* __restrict__ wq,
                            const float* __restrict__ wk,
                            const float* __restrict__ wv,
                            const float* __restrict__ wo) {
    int i = blockIdx.x * 256 + threadIdx.x;
    int w = blockIdx.y;
    const float* src = (w == 0) ? wq : (w == 1) ? wk : (w == 2) ? wv : wo;
    g_Wt[w * WSZ + i] = f2tf32(src[i]);
}

// ---------------------------------------------------------------------------
// Kernel 1: RMSNorm + transpose (t,n,d) -> (n,t,d); tf32 output only
// ---------------------------------------------------------------------------
__global__ void rmsnorm_kernel(const float* __restrict__ x,
                               const float* __restrict__ w) {
    int row = blockIdx.x;          // row = t*128 + n
    int t = row >> 7;
    int n = row & 127;
    int tid = threadIdx.x;

    float4 v = ((const float4*)(x + (size_t)row * D_MOD))[tid];
    float ss = v.x * v.x + v.y * v.y + v.z * v.z + v.w * v.w;
    #pragma unroll
    for (int m = 16; m; m >>= 1) ss += __shfl_xor_sync(0xffffffffu, ss, m);

    __shared__ float sbuf[4];
    if ((tid & 31) == 0) sbuf[tid >> 5] = ss;
    __syncthreads();
    float tot = sbuf[0] + sbuf[1] + sbuf[2] + sbuf[3];
    float inv = rsqrtf(tot * (1.0f / (float)D_MOD) + 1e-6f);

    float4 wv = ((const float4*)w)[tid];
    uint4 ot;
    ot.x = f2tf32(v.x * inv * wv.x);
    ot.y = f2tf32(v.y * inv * wv.y);
    ot.z = f2tf32(v.z * inv * wv.z);
    ot.w = f2tf32(v.w * inv * wv.w);
    ((uint4*)(g_XNt + ((size_t)n * T_SEQ + t) * D_MOD))[tid] = ot;
}

// ---------------------------------------------------------------------------
// GEMM mainloop: C(128x128) = A(128xK) * B(128xK)^T, K=512, tf32 bits in.
// 128 threads, 4 warps, warp tile 64x64. 2-stage cp.async pipeline;
// smem 73728 B -> 3 CTAs/SM. (round-10 proven config)
// ---------------------------------------------------------------------------
#define SMS 36
#define GEMM_STAGE_U (2 * 128 * SMS)            // 9216 words per stage (A+B)
#define GEMM_SMEM_BYTES (2 * GEMM_STAGE_U * 4)  // 73728 B

__device__ __forceinline__ void gemm_mainloop_tf32(
    const uint32_t* __restrict__ A, const uint32_t* __restrict__ B,
    int m0, int n0row, uint32_t* __restrict__ sm,
    float c[4][8][4], int tid)
{
    const int lane = tid & 31;
    const int warp = tid >> 5;      // 0..3
    const int wm = warp & 1;
    const int wn = warp >> 1;
    const int group = lane >> 2;
    const int qk = lane & 3;

    const uint32_t smb = smem_u32(sm);
    const int crow = tid >> 3;          // 0..15
    const int ckq = (tid & 7) << 2;     // 0,4,...,28

    // prologue: chunk 0 -> stage 0
    #pragma unroll
    for (int i = 0; i < 8; i++) {
        int row = crow + i * 16;
        CP_ASYNC16(smb + (uint32_t)(row * SMS + ckq) * 4,
                   A + (size_t)(m0 + row) * 512 + ckq);
        CP_ASYNC16(smb + (uint32_t)(128 * SMS + row * SMS + ckq) * 4,
                   B + (size_t)(n0row + row) * 512 + ckq);
    }
    CP_COMMIT();

    for (int kb = 0; kb < 16; kb++) {
        CP_WAIT0();
        __syncthreads();          // chunk kb visible; stage[(kb+1)&1] free

        const uint32_t* As = sm + (kb & 1) * GEMM_STAGE_U;
        const uint32_t* Bs = As + 128 * SMS;

        if (kb + 1 < 16) {
            uint32_t st = smb + (uint32_t)(((kb + 1) & 1) * GEMM_STAGE_U) * 4;
            int kc = (kb + 1) * 32;
            #pragma unroll
            for (int i = 0; i < 8; i++) {
                int row = crow + i * 16;
                CP_ASYNC16(st + (uint32_t)(row * SMS + ckq) * 4,
                           A + (size_t)(m0 + row) * 512 + kc + ckq);
                CP_ASYNC16(st + (uint32_t)(128 * SMS + row * SMS + ckq) * 4,
                           B + (size_t)(n0row + row) * 512 + kc + ckq);
            }
            CP_COMMIT();
        }

        #pragma unroll
        for (int ks = 0; ks < 4; ks++) {
            int k0 = ks * 8;
            uint32_t af[4][4];
            #pragma unroll
            for (int mt = 0; mt < 4; mt++) {
                int r0 = wm * 64 + mt * 16;
                af[mt][0] = As[(r0 + group) * SMS + k0 + qk];
                af[mt][1] = As[(r0 + 8 + group) * SMS + k0 + qk];
                af[mt][2] = As[(r0 + group) * SMS + k0 + 4 + qk];
                af[mt][3] = As[(r0 + 8 + group) * SMS + k0 + 4 + qk];
            }
            #pragma unroll
            for (int nt = 0; nt < 8; nt++) {
                int nr = wn * 64 + nt * 8;
                uint32_t bf[2];
                bf[0] = Bs[(nr + group) * SMS + k0 + qk];
                bf[1] = Bs[(nr + group) * SMS + k0 + 4 + qk];
                #pragma unroll
                for (int mt = 0; mt < 4; mt++)
                    mma_tf32(c[mt][nt], af[mt], bf);
            }
        }
    }
}

// ---------------------------------------------------------------------------
// Kernel 2: QKV projection (tf32 TC) with FUSED RoPE + q-scale epilogue.
// ---------------------------------------------------------------------------
__global__ void __launch_bounds__(128, 3)
qkv_gemm_tc_kernel() {
    extern __shared__ uint32_t dynsm_u[];

    int n0 = blockIdx.x * 128;
    int m0 = blockIdx.y * 128;
    int which = n0 >> 9;                 // 0=Q, 1=K, 2=V
    int cc0 = n0 & 511;
    uint32_t* Dst = (which == 0) ? g_Q : ((which == 1) ? g_K : g_V);

    int tid = threadIdx.x;
    float c[4][8][4] = {};
    gemm_mainloop_tf32(g_XNt, g_Wt + (size_t)which * WSZ, m0, cc0, dynsm_u, c, tid);

    const int lane = tid & 31;
    const int warp = tid >> 5;
    const int wm = warp & 1, wn = warp >> 1;
    const int group = lane >> 2, qk = lane & 3;

    #pragma unroll
    for (int mt = 0; mt < 4; mt++) {
        #pragma unroll
        for (int half = 0; half < 2; half++) {
            int m = m0 + wm * 64 + mt * 16 + group + half * 8;
            int r = m / T_SEQ;
            int t = m - r * T_SEQ;
            #pragma unroll
            for (int nt = 0; nt < 8; nt++) {
                int col = wn * 64 + nt * 8 + qk * 2;
                int cc = cc0 + col;
                int h = cc >> 6, dh = cc & 63;
                float vx = c[mt][nt][half * 2 + 0];
                float vy = c[mt][nt][half * 2 + 1];
                if (which <= 1 && dh < 32) {
                    int i = dh >> 1;
                    float invf = __expf(-(float)i * 0.57564627324851142f);
                    float sn, cs;
                    sincosf((float)t * invf, &sn, &cs);
                    float a = vx, b = vy;
                    vx = a * cs - b * sn;
                    vy = a * sn + b * cs;
                }
                if (which == 0) { vx *= QSCALE; vy *= QSCALE; }
                uint2 uv = make_uint2(f2tf32(vx), f2tf32(vy));
                *(uint2*)(Dst + (((size_t)(r * H_HEADS + h) * T_SEQ) + t) * DHEAD + dh) = uv;
            }
        }
    }
}

// ---------------------------------------------------------------------------
// Kernel 3: tensor-core causal flash attention.
// q-tile 64, 128 threads. 2-stage cp.async KV ring; Q staged through the
// stage-1 buffer then hoisted to registers. Softmax in exp2 domain with
// DEFERRED-l: per-thread partial row-sums, quad-reduced once in the epilogue
// (removes 4 shuffle latencies from every tile's serial chain).
// P transposed C->A via intra-quad shuffles.
// ---------------------------------------------------------------------------
#define ATT_STR 68
#define ATT_KV_W (2 * 64 * ATT_STR)             // 8704 words per stage (K+V)
#define ATT_SMEM_WORDS (2 * ATT_KV_W)           // 69632 B

__global__ void __launch_bounds__(128, 3)
attn_tc_kernel(const int* __restrict__ pad_mask) {
    extern __shared__ uint32_t smu[];

    const int qt = blockIdx.x;           // 0..5
    const int rh = blockIdx.y;
    const int r = rh >> 3, h = rh & 7;
    const int qbase = qt * 64;

    const int tid = threadIdx.x;
    const int warp = tid >> 5;           // 0..3
    const int lane = tid & 31;
    const int g = lane >> 2;
    const int qk = lane & 3;
    const int wrow = warp * 16;
    const int src1 = (lane & ~3) | (qk >> 1);
    const int src2 = src1 + 2;
    const bool oddqk = (qk & 1);

    const uint32_t smb = smem_u32(smu);
    const int ntiles = qt + 1;

    // prologue: kv tile 0 -> stage 0
    {
        const uint32_t* Kp = g_K + ((size_t)rh * T_SEQ) * DHEAD;
        const uint32_t* Vp = g_V + ((size_t)rh * T_SEQ) * DHEAD;
        #pragma unroll
        for (int i = 0; i < 8; i++) {
            int idx = tid + i * 128;
            int row = idx >> 4, c4 = (idx & 15) << 2;
            CP_ASYNC16(smb + (uint32_t)(row * ATT_STR + c4) * 4,
                       Kp + row * DHEAD + c4);
            CP_ASYNC16(smb + (uint32_t)(64 * ATT_STR + row * ATT_STR + c4) * 4,
                       Vp + row * DHEAD + c4);
        }
        CP_COMMIT();
    }

    // stage Q (64x64) through the stage-1 K region, hoist to registers.
    // Safe: stage 1 is first written by cp.async during iteration kt=0,
    // which is after the loop-top __syncthreads that follows the qf reads.
    {
        uint32_t* Qst = smu + ATT_KV_W;
        const uint32_t* Qp = g_Q + ((size_t)rh * T_SEQ + qbase) * DHEAD;
        #pragma unroll
        for (int i = 0; i < 8; i++) {
            int idx = tid + i * 128;
            int row = idx >> 4, c4 = (idx & 15) << 2;
            *(uint4*)(Qst + row * ATT_STR + c4) = *(const uint4*)(Qp + row * DHEAD + c4);
        }
    }
    __syncthreads();

    uint32_t qf[8][4];
    {
        const uint32_t* Qst = smu + ATT_KV_W;
        #pragma unroll
        for (int ks8 = 0; ks8 < 8; ks8++) {
            int k0 = ks8 * 8;
            qf[ks8][0] = Qst[(wrow + g) * ATT_STR + k0 + qk];
            qf[ks8][1] = Qst[(wrow + 8 + g) * ATT_STR + k0 + qk];
            qf[ks8][2] = Qst[(wrow + g) * ATT_STR + k0 + 4 + qk];
            qf[ks8][3] = Qst[(wrow + 8 + g) * ATT_STR + k0 + 4 + qk];
        }
    }

    float o[8][4] = {};
    float m0r = -1e30f, m1r = -1e30f;
    float lp0 = 0.f, lp1 = 0.f;          // per-thread partial row sums

    for (int kt = 0; kt < ntiles; kt++) {
        const int kbase = kt * 64;
        CP_WAIT0();
        __syncthreads();

        if (kt + 1 < ntiles) {
            const uint32_t* Kp = g_K + ((size_t)rh * T_SEQ + (kt + 1) * 64) * DHEAD;
            const uint32_t* Vp = g_V + ((size_t)rh * T_SEQ + (kt + 1) * 64) * DHEAD;
            uint32_t sb = smb + (uint32_t)(((kt + 1) & 1) * ATT_KV_W) * 4;
            #pragma unroll
            for (int i = 0; i < 8; i++) {
                int idx = tid + i * 128;
                int row = idx >> 4, c4 = (idx & 15) << 2;
                CP_ASYNC16(sb + (uint32_t)(row * ATT_STR + c4) * 4,
                           Kp + row * DHEAD + c4);
                CP_ASYNC16(sb + (uint32_t)(64 * ATT_STR + row * ATT_STR + c4) * 4,
                           Vp + row * DHEAD + c4);
            }
            CP_COMMIT();
        }

        const uint32_t* Ks = smu + (kt & 1) * ATT_KV_W;
        const uint32_t* Vs = Ks + 64 * ATT_STR;

        // ---- S = Q K^T (scores in log2 domain via Q pre-scale) ----
        float s[8][4] = {};
        #pragma unroll
        for (int ks8 = 0; ks8 < 8; ks8++) {
            int k0 = ks8 * 8;
            #pragma unroll
            for (int nt = 0; nt < 8; nt++) {
                uint32_t bf[2];
                bf[0] = Ks[(nt * 8 + g) * ATT_STR + k0 + qk];
                bf[1] = Ks[(nt * 8 + g) * ATT_STR + k0 + 4 + qk];
                mma_tf32(s[nt], qf[ks8], bf);
            }
        }

        const int row0 = qbase + wrow + g;
        const int row1 = row0 + 8;

        // ---- causal mask (only the diagonal tile) ----
        if (kt == qt) {
            #pragma unroll
            for (int nt = 0; nt < 8; nt++) {
                int c0 = kbase + nt * 8 + 2 * qk;
                if (c0 > row0)     s[nt][0] = -1e30f;
                if (c0 + 1 > row0) s[nt][1] = -1e30f;
                if (c0 > row1)     s[nt][2] = -1e30f;
                if (c0 + 1 > row1) s[nt][3] = -1e30f;
            }
        }

        // ---- online softmax (exp2 domain, deferred l) ----
        float tmax0 = -1e30f, tmax1 = -1e30f;
        #pragma unroll
        for (int nt = 0; nt < 8; nt++) {
            tmax0 = fmaxf(tmax0, fmaxf(s[nt][0], s[nt][1]));
            tmax1 = fmaxf(tmax1, fmaxf(s[nt][2], s[nt][3]));
        }
        tmax0 = fmaxf(tmax0, __shfl_xor_sync(0xffffffffu, tmax0, 1));
        tmax0 = fmaxf(tmax0, __shfl_xor_sync(0xffffffffu, tmax0, 2));
        tmax1 = fmaxf(tmax1, __shfl_xor_sync(0xffffffffu, tmax1, 1));
        tmax1 = fmaxf(tmax1, __shfl_xor_sync(0xffffffffu, tmax1, 2));

        float nm0 = fmaxf(m0r, tmax0), nm1 = fmaxf(m1r, tmax1);
        float scl0 = exp2f(m0r - nm0), scl1 = exp2f(m1r - nm1);
        float ts0 = 0.f, ts1 = 0.f;
        #pragma unroll
        for (int nt = 0; nt < 8; nt++) {
            s[nt][0] = exp2f(s[nt][0] - nm0);
            s[nt][1] = exp2f(s[nt][1] - nm0);
            s[nt][2] = exp2f(s[nt][2] - nm1);
            s[nt][3] = exp2f(s[nt][3] - nm1);
            ts0 += s[nt][0] + s[nt][1];
            ts1 += s[nt][2] + s[nt][3];
        }
        // deferred l: per-thread partials only (no shuffles here)
        lp0 = lp0 * scl0 + ts0;
        lp1 = lp1 * scl1 + ts1;
        m0r = nm0; m1r = nm1;
        #pragma unroll
        for (int nt = 0; nt < 8; nt++) {
            o[nt][0] *= scl0; o[nt][1] *= scl0;
            o[nt][2] *= scl1; o[nt][3] *= scl1;
        }

        // ---- O += P @ V (P transposed C->A via intra-quad shuffles) ----
        #pragma unroll
        for (int nt = 0; nt < 8; nt++) {
            float b0 = __shfl_sync(0xffffffffu, s[nt][0], src1);
            float b1 = __shfl_sync(0xffffffffu, s[nt][1], src1);
            float b2 = __shfl_sync(0xffffffffu, s[nt][2], src1);
            float b3 = __shfl_sync(0xffffffffu, s[nt][3], src1);
            float d0 = __shfl_sync(0xffffffffu, s[nt][0], src2);
            float d1 = __shfl_sync(0xffffffffu, s[nt][1], src2);
            float d2 = __shfl_sync(0xffffffffu, s[nt][2], src2);
            float d3 = __shfl_sync(0xffffffffu, s[nt][3], src2);
            uint32_t af[4];
            af[0] = f2tf32(oddqk ? b1 : b0);
            af[1] = f2tf32(oddqk ? b3 : b2);
            af[2] = f2tf32(oddqk ? d1 : d0);
            af[3] = f2tf32(oddqk ? d3 : d2);
            int k0 = nt * 8;
            #pragma unroll
            for (int ot = 0; ot < 8; ot++) {
                uint32_t bf[2];
                bf[0] = Vs[(k0 + qk) * ATT_STR + ot * 8 + g];
                bf[1] = Vs[(k0 + 4 + qk) * ATT_STR + ot * 8 + g];
                mma_tf32(o[ot], af, bf);
            }
        }
    }

    // ---- final l reduction across the quad (once, not per tile) ----
    float l0 = lp0, l1 = lp1;
    l0 += __shfl_xor_sync(0xffffffffu, l0, 1);
    l0 += __shfl_xor_sync(0xffffffffu, l0, 2);
    l1 += __shfl_xor_sync(0xffffffffu, l1, 1);
    l1 += __shfl_xor_sync(0xffffffffu, l1, 2);

    // ---- epilogue: normalize, pad mask, residual (tf32 bits), store ----
    const bool valid = (pad_mask[r] != 0);
    const float inv0 = 1.0f / l0, inv1 = 1.0f / l1;
    const int t0 = qbase + wrow + g;
    const int t1 = t0 + 8;
    #pragma unroll
    for (int nt = 0; nt < 8; nt++) {
        int dh = nt * 8 + 2 * qk;
        const uint32_t* xr0 = g_XNt + ((size_t)r * T_SEQ + t0) * D_MOD + h * DHEAD + dh;
        uint32_t* yp0 = g_Yt + ((size_t)t0 * N_NEU + r) * D_MOD + h * DHEAD + dh;
        uint2 ru0 = *(const uint2*)xr0;
        float ox0 = (valid ? o[nt][0] * inv0 : 0.f) + __uint_as_float(ru0.x);
        float oy0 = (valid ? o[nt][1] * inv0 : 0.f) + __uint_as_float(ru0.y);
        *(uint2*)yp0 = make_uint2(f2tf32(ox0), f2tf32(oy0));

        const uint32_t* xr1 = g_XNt + ((size_t)r * T_SEQ + t1) * D_MOD + h * DHEAD + dh;
        uint32_t* yp1 = g_Yt + ((size_t)t1 * N_NEU + r) * D_MOD + h * DHEAD + dh;
        uint2 ru1 = *(const uint2*)xr1;
        float ox1 = (valid ? o[nt][2] * inv1 : 0.f) + __uint_as_float(ru1.x);
        float oy1 = (valid ? o[nt][3] * inv1 : 0.f) + __uint_as_float(ru1.y);
        *(uint2*)yp1 = make_uint2(f2tf32(ox1), f2tf32(oy1));
    }
}

// ---------------------------------------------------------------------------
// Kernel 4: output projection (tf32 TC, 2-stage cp.async, 3 CTAs/SM).
// ---------------------------------------------------------------------------
__global__ void __launch_bounds__(128, 3)
out_gemm_tc_kernel(float* __restrict__ out) {
    extern __shared__ uint32_t dynsm_u[];

    int n0 = blockIdx.x * 128;
    int m0 = blockIdx.y * 128;
    int tid = threadIdx.x;

    float c[4][8][4] = {};
    gemm_mainloop_tf32(g_Yt, g_Wt + (size_t)3 * WSZ, m0, n0, dynsm_u, c, tid);

    const int lane = tid & 31;
    const int warp = tid >> 5;
    const int wm = warp & 1, wn = warp >> 1;
    const int group = lane >> 2, qk = lane & 3;

    #pragma unroll
    for (int mt = 0; mt < 4; mt++) {
        #pragma unroll
        for (int half = 0; half < 2; half++) {
            int m = m0 + wm * 64 + mt * 16 + group + half * 8;
            #pragma unroll
            for (int nt = 0; nt < 8; nt++) {
                int col = n0 + wn * 64 + nt * 8 + qk * 2;
                float2 v;
                v.x = c[mt][nt][half * 2 + 0];
                v.y = c[mt][nt][half * 2 + 1];
                *(float2*)(out + (size_t)m * 512 + col) = v;
            }
        }
    }
}

// ---------------------------------------------------------------------------
extern "C" void kernel_launch(void* const* d_in, const int* in_sizes, int n_in,
                              void* d_out, int out_size) {
    const float* x       = (const float*)d_in[0];
    const int*   pad     = (const int*)d_in[1];
    const float* norm_w  = (const float*)d_in[2];
    const float* wq      = (const float*)d_in[3];
    const float* wk      = (const float*)d_in[4];
    const float* wv      = (const float*)d_in[5];
    const float* wo      = (const float*)d_in[6];
    float* out = (float*)d_out;
    (void)in_sizes; (void)n_in; (void)out_size;

    cudaFuncSetAttribute(attn_tc_kernel,
                         cudaFuncAttributeMaxDynamicSharedMemorySize,
                         ATT_SMEM_WORDS * 4);
    cudaFuncSetAttribute(qkv_gemm_tc_kernel,
                         cudaFuncAttributeMaxDynamicSharedMemorySize,
                         GEMM_SMEM_BYTES);
    cudaFuncSetAttribute(out_gemm_tc_kernel,
                         cudaFuncAttributeMaxDynamicSharedMemorySize,
                         GEMM_SMEM_BYTES);

    // 0. weights -> tf32
    wcvt_kernel<<<dim3(WSZ / 256, 4), 256>>>(wq, wk, wv, wo);

    // 1. RMSNorm + transpose (tf32 only)
    rmsnorm_kernel<<<M_ROWS, 128>>>(x, norm_w);

    // 2. QKV projection (tf32 TC, 2-stage cp.async, 3 CTAs/SM) + fused RoPE
    qkv_gemm_tc_kernel<<<dim3(1536 / 128, M_ROWS / 128), 128,
                         GEMM_SMEM_BYTES>>>();

    // 3. tensor-core causal attention (q-tile 64, 3 CTAs/SM, deferred-l)
    attn_tc_kernel<<<dim3(T_SEQ / 64, N_NEU * H_HEADS), 128,
                     ATT_SMEM_WORDS * 4>>>(pad);

    // 4. output projection (tf32 TC, 2-stage cp.async, 3 CTAs/SM)
    out_gemm_tc_kernel<<<dim3(512 / 128, M_ROWS / 128), 128,
                         GEMM_SMEM_BYTES>>>(out);
}

// round 15
// speedup vs baseline: 1.3099x; 1.0001x over previous
#include <cuda_runtime.h>
#include <math.h>
#include <stdint.h>

// Problem constants
#define T_SEQ 384
#define N_NEU 128
#define D_MOD 512
#define H_HEADS 8
#define DHEAD 64
#define M_ROWS (N_NEU * T_SEQ)   // 49152
#define QKV_ELEMS (N_NEU * H_HEADS * T_SEQ * DHEAD)  // 25165824
#define WSZ (D_MOD * D_MOD)      // 262144

// Q pre-scale: (1/sqrt(64)) * log2(e) so softmax can use raw exp2
#define QSCALE 0.18033688011112042f

// Scratch (device globals)
__device__ uint32_t g_XNt[N_NEU * T_SEQ * D_MOD];  // tf32 bits (also residual)
__device__ uint32_t g_Q[QKV_ELEMS];                // tf32 bits, rope+scale applied
__device__ uint32_t g_K[QKV_ELEMS];                // tf32 bits, rope applied
__device__ uint32_t g_V[QKV_ELEMS];                // tf32 bits
__device__ uint32_t g_Yt[M_ROWS * D_MOD];          // tf32 bits, (t*128+n, d)
__device__ uint32_t g_Wt[4 * WSZ];                 // tf32 weights: wq,wk,wv,wo

// ---------------------------------------------------------------------------
// helpers
// ---------------------------------------------------------------------------
__device__ __forceinline__ uint32_t f2tf32(float f) {
    uint32_t r;
    asm("cvt.rna.tf32.f32 %0, %1;" : "=r"(r) : "f"(f));
    return r;
}

__device__ __forceinline__ void mma_tf32(float c[4], const uint32_t a[4],
                                         const uint32_t b[2]) {
    asm volatile(
        "mma.sync.aligned.m16n8k8.row.col.f32.tf32.tf32.f32 "
        "{%0,%1,%2,%3}, {%4,%5,%6,%7}, {%8,%9}, {%0,%1,%2,%3};"
        : "+f"(c[0]), "+f"(c[1]), "+f"(c[2]), "+f"(c[3])
        : "r"(a[0]), "r"(a[1]), "r"(a[2]), "r"(a[3]),
          "r"(b[0]), "r"(b[1]));
}

__device__ __forceinline__ uint32_t smem_u32(const void* p) {
    return (uint32_t)__cvta_generic_to_shared(p);
}
#define CP_ASYNC16(dst, src) \
    asm volatile("cp.async.cg.shared.global [%0], [%1], 16;" \
                 :: "r"(dst), "l"(src))
#define CP_COMMIT() asm volatile("cp.async.commit_group;" ::: "memory")
#define CP_WAIT0()  asm volatile("cp.async.wait_group 0;" ::: "memory")

// ---------------------------------------------------------------------------
// Kernel 1: RMSNorm + transpose (blocks < M_ROWS) fused with weight->tf32
// conversion (blocks >= M_ROWS).
// ---------------------------------------------------------------------------
__global__ void rmsnorm_wcvt_kernel(const float* __restrict__ x,
                                    const float* __restrict__ w,
                                    const float* __restrict__ wq,
                                    const float* __restrict__ wk,
                                    const float* __restrict__ wv,
                                    const float* __restrict__ wo) {
    if (blockIdx.x >= M_ROWS) {
        int i = (blockIdx.x - M_ROWS) * 128 + threadIdx.x;   // 0..4*WSZ-1
        int wsel = i >> 18;                                   // WSZ = 2^18
        int j = i & (WSZ - 1);
        const float* src = (wsel == 0) ? wq : (wsel == 1) ? wk
                          : (wsel == 2) ? wv : wo;
        g_Wt[i] = f2tf32(src[j]);
        return;
    }

    int row = blockIdx.x;          // row = t*128 + n
    int t = row >> 7;
    int n = row & 127;
    int tid = threadIdx.x;

    float4 v = ((const float4*)(x + (size_t)row * D_MOD))[tid];
    float ss = v.x * v.x + v.y * v.y + v.z * v.z + v.w * v.w;
    #pragma unroll
    for (int m = 16; m; m >>= 1) ss += __shfl_xor_sync(0xffffffffu, ss, m);

    __shared__ float sbuf[4];
    if ((tid & 31) == 0) sbuf[tid >> 5] = ss;
    __syncthreads();
    float tot = sbuf[0] + sbuf[1] + sbuf[2] + sbuf[3];
    float inv = rsqrtf(tot * (1.0f / (float)D_MOD) + 1e-6f);

    float4 wvec = ((const float4*)w)[tid];
    uint4 ot;
    ot.x = f2tf32(v.x * inv * wvec.x);
    ot.y = f2tf32(v.y * inv * wvec.y);
    ot.z = f2tf32(v.z * inv * wvec.z);
    ot.w = f2tf32(v.w * inv * wvec.w);
    ((uint4*)(g_XNt + ((size_t)n * T_SEQ + t) * D_MOD))[tid] = ot;
}

// ---------------------------------------------------------------------------
// GEMM mainloop: C(128x128) = A(128xK) * B(128xK)^T, K=512, tf32 bits in.
// 128 threads, 4 warps, warp tile 64x64. 2-stage cp.async pipeline;
// smem 73728 B -> 3 CTAs/SM. (round-10 proven config)
// ---------------------------------------------------------------------------
#define SMS 36
#define GEMM_STAGE_U (2 * 128 * SMS)
#define GEMM_SMEM_BYTES (2 * GEMM_STAGE_U * 4)  // 73728 B

__device__ __forceinline__ void gemm_mainloop_tf32(
    const uint32_t* __restrict__ A, const uint32_t* __restrict__ B,
    int m0, int n0row, uint32_t* __restrict__ sm,
    float c[4][8][4], int tid)
{
    const int lane = tid & 31;
    const int warp = tid >> 5;
    const int wm = warp & 1;
    const int wn = warp >> 1;
    const int group = lane >> 2;
    const int qk = lane & 3;

    const uint32_t smb = smem_u32(sm);
    const int crow = tid >> 3;
    const int ckq = (tid & 7) << 2;

    #pragma unroll
    for (int i = 0; i < 8; i++) {
        int row = crow + i * 16;
        CP_ASYNC16(smb + (uint32_t)(row * SMS + ckq) * 4,
                   A + (size_t)(m0 + row) * 512 + ckq);
        CP_ASYNC16(smb + (uint32_t)(128 * SMS + row * SMS + ckq) * 4,
                   B + (size_t)(n0row + row) * 512 + ckq);
    }
    CP_COMMIT();

    for (int kb = 0; kb < 16; kb++) {
        CP_WAIT0();
        __syncthreads();

        const uint32_t* As = sm + (kb & 1) * GEMM_STAGE_U;
        const uint32_t* Bs = As + 128 * SMS;

        if (kb + 1 < 16) {
            uint32_t st = smb + (uint32_t)(((kb + 1) & 1) * GEMM_STAGE_U) * 4;
            int kc = (kb + 1) * 32;
            #pragma unroll
            for (int i = 0; i < 8; i++) {
                int row = crow + i * 16;
                CP_ASYNC16(st + (uint32_t)(row * SMS + ckq) * 4,
                           A + (size_t)(m0 + row) * 512 + kc + ckq);
                CP_ASYNC16(st + (uint32_t)(128 * SMS + row * SMS + ckq) * 4,
                           B + (size_t)(n0row + row) * 512 + kc + ckq);
            }
            CP_COMMIT();
        }

        #pragma unroll
        for (int ks = 0; ks < 4; ks++) {
            int k0 = ks * 8;
            uint32_t af[4][4];
            #pragma unroll
            for (int mt = 0; mt < 4; mt++) {
                int r0 = wm * 64 + mt * 16;
                af[mt][0] = As[(r0 + group) * SMS + k0 + qk];
                af[mt][1] = As[(r0 + 8 + group) * SMS + k0 + qk];
                af[mt][2] = As[(r0 + group) * SMS + k0 + 4 + qk];
                af[mt][3] = As[(r0 + 8 + group) * SMS + k0 + 4 + qk];
            }
            #pragma unroll
            for (int nt = 0; nt < 8; nt++) {
                int nr = wn * 64 + nt * 8;
                uint32_t bf[2];
                bf[0] = Bs[(nr + group) * SMS + k0 + qk];
                bf[1] = Bs[(nr + group) * SMS + k0 + 4 + qk];
                #pragma unroll
                for (int mt = 0; mt < 4; mt++)
                    mma_tf32(c[mt][nt], af[mt], bf);
            }
        }
    }
}

// ---------------------------------------------------------------------------
// Kernel 2: QKV projection (tf32 TC) with FUSED RoPE + q-scale epilogue.
// ---------------------------------------------------------------------------
__global__ void __launch_bounds__(128, 3)
qkv_gemm_tc_kernel() {
    extern __shared__ uint32_t dynsm_u[];

    int n0 = blockIdx.x * 128;
    int m0 = blockIdx.y * 128;
    int which = n0 >> 9;                 // 0=Q, 1=K, 2=V
    int cc0 = n0 & 511;
    uint32_t* Dst = (which == 0) ? g_Q : ((which == 1) ? g_K : g_V);

    int tid = threadIdx.x;
    float c[4][8][4] = {};
    gemm_mainloop_tf32(g_XNt, g_Wt + (size_t)which * WSZ, m0, cc0, dynsm_u, c, tid);

    const int lane = tid & 31;
    const int warp = tid >> 5;
    const int wm = warp & 1, wn = warp >> 1;
    const int group = lane >> 2, qk = lane & 3;

    #pragma unroll
    for (int mt = 0; mt < 4; mt++) {
        #pragma unroll
        for (int half = 0; half < 2; half++) {
            int m = m0 + wm * 64 + mt * 16 + group + half * 8;
            int r = m / T_SEQ;
            int t = m - r * T_SEQ;
            #pragma unroll
            for (int nt = 0; nt < 8; nt++) {
                int col = wn * 64 + nt * 8 + qk * 2;
                int cc = cc0 + col;
                int h = cc >> 6, dh = cc & 63;
                float vx = c[mt][nt][half * 2 + 0];
                float vy = c[mt][nt][half * 2 + 1];
                if (which <= 1 && dh < 32) {
                    int i = dh >> 1;
                    float invf = __expf(-(float)i * 0.57564627324851142f);
                    float sn, cs;
                    sincosf((float)t * invf, &sn, &cs);
                    float a = vx, b = vy;
                    vx = a * cs - b * sn;
                    vy = a * sn + b * cs;
                }
                if (which == 0) { vx *= QSCALE; vy *= QSCALE; }
                uint2 uv = make_uint2(f2tf32(vx), f2tf32(vy));
                *(uint2*)(Dst + (((size_t)(r * H_HEADS + h) * T_SEQ) + t) * DHEAD + dh) = uv;
            }
        }
    }
}

// ---------------------------------------------------------------------------
// Kernel 3: tensor-core causal flash attention.
// q-tile 64, 128 threads, 3 CTAs/SM. 2-stage cp.async KV ring; Q through the
// stage-1 buffer then registers. Softmax exp2-domain, deferred l.
// Main loop handles kt < qt with NO masking; the diagonal tile is handled
// separately with per-warp reduced column range (ntmax = 2*warp+1).
// ---------------------------------------------------------------------------
#define ATT_STR 68
#define ATT_KV_W (2 * 64 * ATT_STR)             // 8704 words per stage (K+V)
#define ATT_SMEM_WORDS (2 * ATT_KV_W)           // 69632 B

__global__ void __launch_bounds__(128, 3)
attn_tc_kernel(const int* __restrict__ pad_mask) {
    extern __shared__ uint32_t smu[];

    const int qt = blockIdx.x;           // 0..5
    const int rh = blockIdx.y;
    const int r = rh >> 3, h = rh & 7;
    const int qbase = qt * 64;

    const int tid = threadIdx.x;
    const int warp = tid >> 5;           // 0..3
    const int lane = tid & 31;
    const int g = lane >> 2;
    const int qk = lane & 3;
    const int wrow = warp * 16;
    const int src1 = (lane & ~3) | (qk >> 1);
    const int src2 = src1 + 2;
    const bool oddqk = (qk & 1);

    const uint32_t smb = smem_u32(smu);

    // prologue: kv tile 0 -> stage 0
    {
        const uint32_t* Kp = g_K + ((size_t)rh * T_SEQ) * DHEAD;
        const uint32_t* Vp = g_V + ((size_t)rh * T_SEQ) * DHEAD;
        #pragma unroll
        for (int i = 0; i < 8; i++) {
            int idx = tid + i * 128;
            int row = idx >> 4, c4 = (idx & 15) << 2;
            CP_ASYNC16(smb + (uint32_t)(row * ATT_STR + c4) * 4,
                       Kp + row * DHEAD + c4);
            CP_ASYNC16(smb + (uint32_t)(64 * ATT_STR + row * ATT_STR + c4) * 4,
                       Vp + row * DHEAD + c4);
        }
        CP_COMMIT();
    }

    // stage Q (64x64) through the stage-1 K region, hoist to registers.
    {
        uint32_t* Qst = smu + ATT_KV_W;
        const uint32_t* Qp = g_Q + ((size_t)rh * T_SEQ + qbase) * DHEAD;
        #pragma unroll
        for (int i = 0; i < 8; i++) {
            int idx = tid + i * 128;
            int row = idx >> 4, c4 = (idx & 15) << 2;
            *(uint4*)(Qst + row * ATT_STR + c4) = *(const uint4*)(Qp + row * DHEAD + c4);
        }
    }
    __syncthreads();

    uint32_t qf[8][4];
    {
        const uint32_t* Qst = smu + ATT_KV_W;
        #pragma unroll
        for (int ks8 = 0; ks8 < 8; ks8++) {
            int k0 = ks8 * 8;
            qf[ks8][0] = Qst[(wrow + g) * ATT_STR + k0 + qk];
            qf[ks8][1] = Qst[(wrow + 8 + g) * ATT_STR + k0 + qk];
            qf[ks8][2] = Qst[(wrow + g) * ATT_STR + k0 + 4 + qk];
            qf[ks8][3] = Qst[(wrow + 8 + g) * ATT_STR + k0 + 4 + qk];
        }
    }

    float o[8][4] = {};
    float m0r = -1e30f, m1r = -1e30f;
    float lp0 = 0.f, lp1 = 0.f;          // per-thread partial row sums

    // ======================= main loop: full tiles, no masks ==============
    for (int kt = 0; kt < qt; kt++) {
        CP_WAIT0();
        __syncthreads();

        // prefetch tile kt+1 (always exists: kt+1 <= qt)
        {
            const uint32_t* Kp = g_K + ((size_t)rh * T_SEQ + (kt + 1) * 64) * DHEAD;
            const uint32_t* Vp = g_V + ((size_t)rh * T_SEQ + (kt + 1) * 64) * DHEAD;
            uint32_t sb = smb + (uint32_t)(((kt + 1) & 1) * ATT_KV_W) * 4;
            #pragma unroll
            for (int i = 0; i < 8; i++) {
                int idx = tid + i * 128;
                int row = idx >> 4, c4 = (idx & 15) << 2;
                CP_ASYNC16(sb + (uint32_t)(row * ATT_STR + c4) * 4,
                           Kp + row * DHEAD + c4);
                CP_ASYNC16(sb + (uint32_t)(64 * ATT_STR + row * ATT_STR + c4) * 4,
                           Vp + row * DHEAD + c4);
            }
            CP_COMMIT();
        }

        const uint32_t* Ks = smu + (kt & 1) * ATT_KV_W;
        const uint32_t* Vs = Ks + 64 * ATT_STR;

        float s[8][4] = {};
        #pragma unroll
        for (int ks8 = 0; ks8 < 8; ks8++) {
            int k0 = ks8 * 8;
            #pragma unroll
            for (int nt = 0; nt < 8; nt++) {
                uint32_t bf[2];
                bf[0] = Ks[(nt * 8 + g) * ATT_STR + k0 + qk];
                bf[1] = Ks[(nt * 8 + g) * ATT_STR + k0 + 4 + qk];
                mma_tf32(s[nt], qf[ks8], bf);
            }
        }

        float tmax0 = -1e30f, tmax1 = -1e30f;
        #pragma unroll
        for (int nt = 0; nt < 8; nt++) {
            tmax0 = fmaxf(tmax0, fmaxf(s[nt][0], s[nt][1]));
            tmax1 = fmaxf(tmax1, fmaxf(s[nt][2], s[nt][3]));
        }
        tmax0 = fmaxf(tmax0, __shfl_xor_sync(0xffffffffu, tmax0, 1));
        tmax0 = fmaxf(tmax0, __shfl_xor_sync(0xffffffffu, tmax0, 2));
        tmax1 = fmaxf(tmax1, __shfl_xor_sync(0xffffffffu, tmax1, 1));
        tmax1 = fmaxf(tmax1, __shfl_xor_sync(0xffffffffu, tmax1, 2));

        float nm0 = fmaxf(m0r, tmax0), nm1 = fmaxf(m1r, tmax1);
        float scl0 = exp2f(m0r - nm0), scl1 = exp2f(m1r - nm1);
        float ts0 = 0.f, ts1 = 0.f;
        #pragma unroll
        for (int nt = 0; nt < 8; nt++) {
            s[nt][0] = exp2f(s[nt][0] - nm0);
            s[nt][1] = exp2f(s[nt][1] - nm0);
            s[nt][2] = exp2f(s[nt][2] - nm1);
            s[nt][3] = exp2f(s[nt][3] - nm1);
            ts0 += s[nt][0] + s[nt][1];
            ts1 += s[nt][2] + s[nt][3];
        }
        lp0 = lp0 * scl0 + ts0;
        lp1 = lp1 * scl1 + ts1;
        m0r = nm0; m1r = nm1;
        #pragma unroll
        for (int nt = 0; nt < 8; nt++) {
            o[nt][0] *= scl0; o[nt][1] *= scl0;
            o[nt][2] *= scl1; o[nt][3] *= scl1;
        }

        #pragma unroll
        for (int nt = 0; nt < 8; nt++) {
            float b0 = __shfl_sync(0xffffffffu, s[nt][0], src1);
            float b1 = __shfl_sync(0xffffffffu, s[nt][1], src1);
            float b2 = __shfl_sync(0xffffffffu, s[nt][2], src1);
            float b3 = __shfl_sync(0xffffffffu, s[nt][3], src1);
            float d0 = __shfl_sync(0xffffffffu, s[nt][0], src2);
            float d1 = __shfl_sync(0xffffffffu, s[nt][1], src2);
            float d2 = __shfl_sync(0xffffffffu, s[nt][2], src2);
            float d3 = __shfl_sync(0xffffffffu, s[nt][3], src2);
            uint32_t af[4];
            af[0] = f2tf32(oddqk ? b1 : b0);
            af[1] = f2tf32(oddqk ? b3 : b2);
            af[2] = f2tf32(oddqk ? d1 : d0);
            af[3] = f2tf32(oddqk ? d3 : d2);
            int k0 = nt * 8;
            #pragma unroll
            for (int ot = 0; ot < 8; ot++) {
                uint32_t bf[2];
                bf[0] = Vs[(k0 + qk) * ATT_STR + ot * 8 + g];
                bf[1] = Vs[(k0 + 4 + qk) * ATT_STR + ot * 8 + g];
                mma_tf32(o[ot], af, bf);
            }
        }
    }

    // ======================= diagonal tile (kt = qt) ======================
    {
        CP_WAIT0();
        __syncthreads();

        const uint32_t* Ks = smu + (qt & 1) * ATT_KV_W;
        const uint32_t* Vs = Ks + 64 * ATT_STR;
        const int ntmax = 2 * warp + 1;      // warp-uniform column-block bound
        const int kbase = qbase;

        float s[8][4] = {};
        #pragma unroll
        for (int ks8 = 0; ks8 < 8; ks8++) {
            int k0 = ks8 * 8;
            #pragma unroll
            for (int nt = 0; nt < 8; nt++) {
                if (nt <= ntmax) {
                    uint32_t bf[2];
                    bf[0] = Ks[(nt * 8 + g) * ATT_STR + k0 + qk];
                    bf[1] = Ks[(nt * 8 + g) * ATT_STR + k0 + 4 + qk];
                    mma_tf32(s[nt], qf[ks8], bf);
                }
            }
        }

        const int row0 = qbase + wrow + g;
        const int row1 = row0 + 8;

        #pragma unroll
        for (int nt = 0; nt < 8; nt++) {
            if (nt <= ntmax) {
                int c0 = kbase + nt * 8 + 2 * qk;
                if (c0 > row0)     s[nt][0] = -1e30f;
                if (c0 + 1 > row0) s[nt][1] = -1e30f;
                if (c0 > row1)     s[nt][2] = -1e30f;
                if (c0 + 1 > row1) s[nt][3] = -1e30f;
            }
        }

        float tmax0 = -1e30f, tmax1 = -1e30f;
        #pragma unroll
        for (int nt = 0; nt < 8; nt++) {
            if (nt <= ntmax) {
                tmax0 = fmaxf(tmax0, fmaxf(s[nt][0], s[nt][1]));
                tmax1 = fmaxf(tmax1, fmaxf(s[nt][2], s[nt][3]));
            }
        }
        tmax0 = fmaxf(tmax0, __shfl_xor_sync(0xffffffffu, tmax0, 1));
        tmax0 = fmaxf(tmax0, __shfl_xor_sync(0xffffffffu, tmax0, 2));
        tmax1 = fmaxf(tmax1, __shfl_xor_sync(0xffffffffu, tmax1, 1));
        tmax1 = fmaxf(tmax1, __shfl_xor_sync(0xffffffffu, tmax1, 2));

        float nm0 = fmaxf(m0r, tmax0), nm1 = fmaxf(m1r, tmax1);
        float scl0 = exp2f(m0r - nm0), scl1 = exp2f(m1r - nm1);
        float ts0 = 0.f, ts1 = 0.f;
        #pragma unroll
        for (int nt = 0; nt < 8; nt++) {
            if (nt <= ntmax) {
                s[nt][0] = exp2f(s[nt][0] - nm0);
                s[nt][1] = exp2f(s[nt][1] - nm0);
                s[nt][2] = exp2f(s[nt][2] - nm1);
                s[nt][3] = exp2f(s[nt][3] - nm1);
                ts0 += s[nt][0] + s[nt][1];
                ts1 += s[nt][2] + s[nt][3];
            }
        }
        lp0 = lp0 * scl0 + ts0;
        lp1 = lp1 * scl1 + ts1;
        #pragma unroll
        for (int nt = 0; nt < 8; nt++) {
            o[nt][0] *= scl0; o[nt][1] *= scl0;
            o[nt][2] *= scl1; o[nt][3] *= scl1;
        }

        #pragma unroll
        for (int nt = 0; nt < 8; nt++) {
            if (nt <= ntmax) {        // warp-uniform: shuffles stay collective
                float b0 = __shfl_sync(0xffffffffu, s[nt][0], src1);
                float b1 = __shfl_sync(0xffffffffu, s[nt][1], src1);
                float b2 = __shfl_sync(0xffffffffu, s[nt][2], src1);
                float b3 = __shfl_sync(0xffffffffu, s[nt][3], src1);
                float d0 = __shfl_sync(0xffffffffu, s[nt][0], src2);
                float d1 = __shfl_sync(0xffffffffu, s[nt][1], src2);
                float d2 = __shfl_sync(0xffffffffu, s[nt][2], src2);
                float d3 = __shfl_sync(0xffffffffu, s[nt][3], src2);
                uint32_t af[4];
                af[0] = f2tf32(oddqk ? b1 : b0);
                af[1] = f2tf32(oddqk ? b3 : b2);
                af[2] = f2tf32(oddqk ? d1 : d0);
                af[3] = f2tf32(oddqk ? d3 : d2);
                int k0 = nt * 8;
                #pragma unroll
                for (int ot = 0; ot < 8; ot++) {
                    uint32_t bf[2];
                    bf[0] = Vs[(k0 + qk) * ATT_STR + ot * 8 + g];
                    bf[1] = Vs[(k0 + 4 + qk) * ATT_STR + ot * 8 + g];
                    mma_tf32(o[ot], af, bf);
                }
            }
        }
    }

    // ---- final l reduction across the quad ----
    float l0 = lp0, l1 = lp1;
    l0 += __shfl_xor_sync(0xffffffffu, l0, 1);
    l0 += __shfl_xor_sync(0xffffffffu, l0, 2);
    l1 += __shfl_xor_sync(0xffffffffu, l1, 1);
    l1 += __shfl_xor_sync(0xffffffffu, l1, 2);

    // ---- epilogue: normalize, pad mask, residual (tf32 bits), store ----
    const bool valid = (pad_mask[r] != 0);
    const float inv0 = 1.0f / l0, inv1 = 1.0f / l1;
    const int t0 = qbase + wrow + g;
    const int t1 = t0 + 8;
    #pragma unroll
    for (int nt = 0; nt < 8; nt++) {
        int dh = nt * 8 + 2 * qk;
        const uint32_t* xr0 = g_XNt + ((size_t)r * T_SEQ + t0) * D_MOD + h * DHEAD + dh;
        uint32_t* yp0 = g_Yt + ((size_t)t0 * N_NEU + r) * D_MOD + h * DHEAD + dh;
        uint2 ru0 = *(const uint2*)xr0;
        float ox0 = (valid ? o[nt][0] * inv0 : 0.f) + __uint_as_float(ru0.x);
        float oy0 = (valid ? o[nt][1] * inv0 : 0.f) + __uint_as_float(ru0.y);
        *(uint2*)yp0 = make_uint2(f2tf32(ox0), f2tf32(oy0));

        const uint32_t* xr1 = g_XNt + ((size_t)r * T_SEQ + t1) * D_MOD + h * DHEAD + dh;
        uint32_t* yp1 = g_Yt + ((size_t)t1 * N_NEU + r) * D_MOD + h * DHEAD + dh;
        uint2 ru1 = *(const uint2*)xr1;
        float ox1 = (valid ? o[nt][2] * inv1 : 0.f) + __uint_as_float(ru1.x);
        float oy1 = (valid ? o[nt][3] * inv1 : 0.f) + __uint_as_float(ru1.y);
        *(uint2*)yp1 = make_uint2(f2tf32(ox1), f2tf32(oy1));
    }
}

// ---------------------------------------------------------------------------
// Kernel 4: output projection (tf32 TC, 2-stage cp.async, 3 CTAs/SM).
// ---------------------------------------------------------------------------
__global__ void __launch_bounds__(128, 3)
out_gemm_tc_kernel(float* __restrict__ out) {
    extern __shared__ uint32_t dynsm_u[];

    int n0 = blockIdx.x * 128;
    int m0 = blockIdx.y * 128;
    int tid = threadIdx.x;

    float c[4][8][4] = {};
    gemm_mainloop_tf32(g_Yt, g_Wt + (size_t)3 * WSZ, m0, n0, dynsm_u, c, tid);

    const int lane = tid & 31;
    const int warp = tid >> 5;
    const int wm = warp & 1, wn = warp >> 1;
    const int group = lane >> 2, qk = lane & 3;

    #pragma unroll
    for (int mt = 0; mt < 4; mt++) {
        #pragma unroll
        for (int half = 0; half < 2; half++) {
            int m = m0 + wm * 64 + mt * 16 + group + half * 8;
            #pragma unroll
            for (int nt = 0; nt < 8; nt++) {
                int col = n0 + wn * 64 + nt * 8 + qk * 2;
                float2 v;
                v.x = c[mt][nt][half * 2 + 0];
                v.y = c[mt][nt][half * 2 + 1];
                *(float2*)(out + (size_t)m * 512 + col) = v;
            }
        }
    }
}

// ---------------------------------------------------------------------------
extern "C" void kernel_launch(void* const* d_in, const int* in_sizes, int n_in,
                              void* d_out, int out_size) {
    const float* x       = (const float*)d_in[0];
    const int*   pad     = (const int*)d_in[1];
    const float* norm_w  = (const float*)d_in[2];
    const float* wq      = (const float*)d_in[3];
    const float* wk      = (const float*)d_in[4];
    const float* wv      = (const float*)d_in[5];
    const float* wo      = (const float*)d_in[6];
    float* out = (float*)d_out;
    (void)in_sizes; (void)n_in; (void)out_size;

    cudaFuncSetAttribute(attn_tc_kernel,
                         cudaFuncAttributeMaxDynamicSharedMemorySize,
                         ATT_SMEM_WORDS * 4);
    cudaFuncSetAttribute(qkv_gemm_tc_kernel,
                         cudaFuncAttributeMaxDynamicSharedMemorySize,
                         GEMM_SMEM_BYTES);
    cudaFuncSetAttribute(out_gemm_tc_kernel,
                         cudaFuncAttributeMaxDynamicSharedMemorySize,
                         GEMM_SMEM_BYTES);

    // 1. RMSNorm + transpose (tf32) fused with weights -> tf32
    rmsnorm_wcvt_kernel<<<M_ROWS + 4 * WSZ / 128, 128>>>(x, norm_w,
                                                         wq, wk, wv, wo);

    // 2. QKV projection (tf32 TC, 2-stage cp.async, 3 CTAs/SM) + fused RoPE
    qkv_gemm_tc_kernel<<<dim3(1536 / 128, M_ROWS / 128), 128,
                         GEMM_SMEM_BYTES>>>();

    // 3. tensor-core causal attention (diagonal-split, 3 CTAs/SM)
    attn_tc_kernel<<<dim3(T_SEQ / 64, N_NEU * H_HEADS), 128,
                     ATT_SMEM_WORDS * 4>>>(pad);

    // 4. output projection (tf32 TC, 2-stage cp.async, 3 CTAs/SM)
    out_gemm_tc_kernel<<<dim3(512 / 128, M_ROWS / 128), 128,
                         GEMM_SMEM_BYTES>>>(out);
}

// round 16
// speedup vs baseline: 2.1582x; 1.6476x over previous
#include <cuda_runtime.h>
#include <cuda_fp16.h>
#include <math.h>
#include <stdint.h>

// Problem constants
#define T_SEQ 384
#define N_NEU 128
#define D_MOD 512
#define H_HEADS 8
#define DHEAD 64
#define M_ROWS (N_NEU * T_SEQ)   // 49152
#define QKV_ELEMS (N_NEU * H_HEADS * T_SEQ * DHEAD)  // 25165824
#define WSZ (D_MOD * D_MOD)      // 262144

// Q pre-scale: (1/sqrt(64)) * log2(e) so softmax can use raw exp2
#define QSCALE 0.18033688011112042f

// Scratch (device globals) — fp16 storage everywhere (10-bit mantissa = tf32)
__device__ __half g_XNh[N_NEU * T_SEQ * D_MOD];   // rmsnormed x (also residual)
__device__ __half g_Q[QKV_ELEMS];                 // (rh, t, dh), rope+scale
__device__ __half g_K[QKV_ELEMS];                 // (rh, t, dh), rope
__device__ __half g_VT[QKV_ELEMS];                // (rh, dh, t)  TRANSPOSED
__device__ __half g_Yt[M_ROWS * D_MOD];           // (t*128+n, d)
__device__ __half g_Wh[4 * WSZ];                  // weights: wq,wk,wv,wo

// ---------------------------------------------------------------------------
// helpers
// ---------------------------------------------------------------------------
__device__ __forceinline__ uint32_t pack_h2(float x, float y) {
    __half2 h = __floats2half2_rn(x, y);   // x -> low half
    return *(uint32_t*)&h;
}

__device__ __forceinline__ void mma_f16(float c[4], const uint32_t a[4],
                                        const uint32_t b[2]) {
    asm volatile(
        "mma.sync.aligned.m16n8k16.row.col.f32.f16.f16.f32 "
        "{%0,%1,%2,%3}, {%4,%5,%6,%7}, {%8,%9}, {%0,%1,%2,%3};"
        : "+f"(c[0]), "+f"(c[1]), "+f"(c[2]), "+f"(c[3])
        : "r"(a[0]), "r"(a[1]), "r"(a[2]), "r"(a[3]),
          "r"(b[0]), "r"(b[1]));
}

__device__ __forceinline__ uint32_t smem_u32(const void* p) {
    return (uint32_t)__cvta_generic_to_shared(p);
}
#define CP_ASYNC16(dst, src) \
    asm volatile("cp.async.cg.shared.global [%0], [%1], 16;" \
                 :: "r"(dst), "l"(src))
#define CP_COMMIT() asm volatile("cp.async.commit_group;" ::: "memory")
#define CP_WAIT0()  asm volatile("cp.async.wait_group 0;" ::: "memory")

// ---------------------------------------------------------------------------
// Kernel 1: RMSNorm + transpose (blocks < M_ROWS) fused with weight->fp16
// conversion (blocks >= M_ROWS, 256 weight elems per block).
// ---------------------------------------------------------------------------
__global__ void rmsnorm_wcvt_kernel(const float* __restrict__ x,
                                    const float* __restrict__ w,
                                    const float* __restrict__ wq,
                                    const float* __restrict__ wk,
                                    const float* __restrict__ wv,
                                    const float* __restrict__ wo) {
    if (blockIdx.x >= M_ROWS) {
        int i = ((blockIdx.x - M_ROWS) * 128 + threadIdx.x) * 2; // 0..4*WSZ-2
        int wsel = i >> 18;                                       // WSZ = 2^18
        int j = i & (WSZ - 1);
        const float* src = (wsel == 0) ? wq : (wsel == 1) ? wk
                          : (wsel == 2) ? wv : wo;
        *(uint32_t*)&g_Wh[i] = pack_h2(src[j], src[j + 1]);
        return;
    }

    int row = blockIdx.x;          // row = t*128 + n
    int t = row >> 7;
    int n = row & 127;
    int tid = threadIdx.x;

    float4 v = ((const float4*)(x + (size_t)row * D_MOD))[tid];
    float ss = v.x * v.x + v.y * v.y + v.z * v.z + v.w * v.w;
    #pragma unroll
    for (int m = 16; m; m >>= 1) ss += __shfl_xor_sync(0xffffffffu, ss, m);

    __shared__ float sbuf[4];
    if ((tid & 31) == 0) sbuf[tid >> 5] = ss;
    __syncthreads();
    float tot = sbuf[0] + sbuf[1] + sbuf[2] + sbuf[3];
    float inv = rsqrtf(tot * (1.0f / (float)D_MOD) + 1e-6f);

    float4 wvec = ((const float4*)w)[tid];
    uint2 ot;
    ot.x = pack_h2(v.x * inv * wvec.x, v.y * inv * wvec.y);
    ot.y = pack_h2(v.z * inv * wvec.z, v.w * inv * wvec.w);
    *(uint2*)&g_XNh[((size_t)n * T_SEQ + t) * D_MOD + 4 * tid] = ot;
}

// ---------------------------------------------------------------------------
// GEMM mainloop: C(128x128) = A(128xK) * B(128xK)^T, K=512, fp16 in/fp32 acc.
// 128 threads, 4 warps, warp tile 64x64, mma m16n8k16.
// K-chunk 64 halfs (128 B/row), 2-stage cp.async pipeline.
// smem: row stride 72 halfs (144 B: 16B-aligned, conflict-free LDS.32).
// 2 stages x 2 x 128 x 72 halfs = 73728 B -> 3 CTAs/SM.
// ---------------------------------------------------------------------------
#define STRH 72
#define GEMM_STAGE_H (2 * 128 * STRH)           // 18432 halfs per stage (A+B)
#define GEMM_SMEM_BYTES (2 * GEMM_STAGE_H * 2)  // 73728 B

__device__ __forceinline__ void gemm_mainloop_f16(
    const __half* __restrict__ A, const __half* __restrict__ B,
    int m0, int n0row, __half* __restrict__ sm,
    float c[4][8][4], int tid)
{
    const int lane = tid & 31;
    const int warp = tid >> 5;
    const int wm = warp & 1;
    const int wn = warp >> 1;
    const int g = lane >> 2;
    const int qk2 = (lane & 3) * 2;

    const uint32_t smb = smem_u32(sm);
    const int crow = tid >> 3;          // 0..15 (+16*i)
    const int cu = tid & 7;             // 16B unit within 128B row

    // prologue: chunk 0 (k 0..63) -> stage 0
    #pragma unroll
    for (int i = 0; i < 8; i++) {
        int row = crow + i * 16;
        CP_ASYNC16(smb + (uint32_t)(row * 144 + cu * 16),
                   A + (size_t)(m0 + row) * 512 + cu * 8);
        CP_ASYNC16(smb + (uint32_t)(128 * 144 + row * 144 + cu * 16),
                   B + (size_t)(n0row + row) * 512 + cu * 8);
    }
    CP_COMMIT();

    for (int kb = 0; kb < 8; kb++) {
        CP_WAIT0();
        __syncthreads();

        const __half* As = sm + (kb & 1) * GEMM_STAGE_H;
        const __half* Bs = As + 128 * STRH;

        if (kb + 1 < 8) {
            uint32_t st = smb + (uint32_t)(((kb + 1) & 1) * GEMM_STAGE_H) * 2;
            int kc = (kb + 1) * 64;
            #pragma unroll
            for (int i = 0; i < 8; i++) {
                int row = crow + i * 16;
                CP_ASYNC16(st + (uint32_t)(row * 144 + cu * 16),
                           A + (size_t)(m0 + row) * 512 + kc + cu * 8);
                CP_ASYNC16(st + (uint32_t)(128 * 144 + row * 144 + cu * 16),
                           B + (size_t)(n0row + row) * 512 + kc + cu * 8);
            }
            CP_COMMIT();
        }

        #pragma unroll
        for (int ks = 0; ks < 4; ks++) {
            int k0 = ks * 16;
            uint32_t af[4][4];
            #pragma unroll
            for (int mt = 0; mt < 4; mt++) {
                int r0 = wm * 64 + mt * 16;
                af[mt][0] = *(const uint32_t*)&As[(r0 + g) * STRH + k0 + qk2];
                af[mt][1] = *(const uint32_t*)&As[(r0 + 8 + g) * STRH + k0 + qk2];
                af[mt][2] = *(const uint32_t*)&As[(r0 + g) * STRH + k0 + 8 + qk2];
                af[mt][3] = *(const uint32_t*)&As[(r0 + 8 + g) * STRH + k0 + 8 + qk2];
            }
            #pragma unroll
            for (int nt = 0; nt < 8; nt++) {
                int nr = wn * 64 + nt * 8;
                uint32_t bf[2];
                bf[0] = *(const uint32_t*)&Bs[(nr + g) * STRH + k0 + qk2];
                bf[1] = *(const uint32_t*)&Bs[(nr + g) * STRH + k0 + 8 + qk2];
                #pragma unroll
                for (int mt = 0; mt < 4; mt++)
                    mma_f16(c[mt][nt], af[mt], bf);
            }
        }
    }
}

// ---------------------------------------------------------------------------
// Kernel 2: QKV projection (fp16 TC) + fused RoPE / q-scale.
// Q/K written (rh,t,dh); V written TRANSPOSED (rh,dh,t).
// ---------------------------------------------------------------------------
__global__ void __launch_bounds__(128, 3)
qkv_gemm_tc_kernel() {
    extern __shared__ __half dynsm_h[];

    int n0 = blockIdx.x * 128;
    int m0 = blockIdx.y * 128;
    int which = n0 >> 9;                 // 0=Q, 1=K, 2=V
    int cc0 = n0 & 511;

    int tid = threadIdx.x;
    float c[4][8][4] = {};
    gemm_mainloop_f16(g_XNh, g_Wh + (size_t)which * WSZ, m0, cc0, dynsm_h, c, tid);

    const int lane = tid & 31;
    const int warp = tid >> 5;
    const int wm = warp & 1, wn = warp >> 1;
    const int g = lane >> 2, qk = lane & 3;

    #pragma unroll
    for (int mt = 0; mt < 4; mt++) {
        #pragma unroll
        for (int half_i = 0; half_i < 2; half_i++) {
            int m = m0 + wm * 64 + mt * 16 + g + half_i * 8;
            int r = m / T_SEQ;
            int t = m - r * T_SEQ;
            #pragma unroll
            for (int nt = 0; nt < 8; nt++) {
                int col = wn * 64 + nt * 8 + qk * 2;
                int cc = cc0 + col;
                int h = cc >> 6, dh = cc & 63;
                float vx = c[mt][nt][half_i * 2 + 0];
                float vy = c[mt][nt][half_i * 2 + 1];
                if (which <= 1 && dh < 32) {
                    int i = dh >> 1;
                    float invf = __expf(-(float)i * 0.57564627324851142f);
                    float sn, cs;
                    sincosf((float)t * invf, &sn, &cs);
                    float a = vx, b = vy;
                    vx = a * cs - b * sn;
                    vy = a * sn + b * cs;
                }
                size_t rh = (size_t)(r * H_HEADS + h);
                if (which == 0) {
                    vx *= QSCALE; vy *= QSCALE;
                    *(uint32_t*)&g_Q[(rh * T_SEQ + t) * DHEAD + dh] = pack_h2(vx, vy);
                } else if (which == 1) {
                    *(uint32_t*)&g_K[(rh * T_SEQ + t) * DHEAD + dh] = pack_h2(vx, vy);
                } else {
                    g_VT[(rh * DHEAD + dh) * T_SEQ + t]     = __float2half_rn(vx);
                    g_VT[(rh * DHEAD + dh + 1) * T_SEQ + t] = __float2half_rn(vy);
                }
            }
        }
    }
}

// ---------------------------------------------------------------------------
// Kernel 3: fp16 tensor-core causal flash attention.
// q-tile 64, 128 threads, 4 CTAs/SM. 2-stage cp.async KV ring (K + V^T);
// Q staged through stage-1 then registers. Softmax exp2-domain, deferred l.
// P packed to fp16 A-fragments DIRECTLY (no shuffles). Diagonal tile split
// with warp-uniform ntmax.
// ---------------------------------------------------------------------------
#define ATT_STAGE_H (2 * 64 * STRH)              // 9216 halfs per stage (K+VT)
#define ATT_SMEM_BYTES (2 * ATT_STAGE_H * 2)     // 36864 B

__global__ void __launch_bounds__(128, 4)
attn_tc_kernel(const int* __restrict__ pad_mask) {
    extern __shared__ __half smh[];

    const int qt = blockIdx.x;           // 0..5
    const int rh = blockIdx.y;
    const int r = rh >> 3, h = rh & 7;
    const int qbase = qt * 64;

    const int tid = threadIdx.x;
    const int warp = tid >> 5;           // 0..3
    const int lane = tid & 31;
    const int g = lane >> 2;
    const int qk = lane & 3;
    const int qk2 = qk * 2;
    const int wrow = warp * 16;

    const uint32_t smb = smem_u32(smh);
    const int crow = tid >> 3;           // 0..15 (+16*i)
    const int cu = tid & 7;

    const __half* Kg = g_K + (size_t)rh * T_SEQ * DHEAD;
    const __half* VTg = g_VT + (size_t)rh * DHEAD * T_SEQ;

    // prologue: kv tile 0 -> stage 0 (K rows kv x d; VT rows dh x t)
    #pragma unroll
    for (int i = 0; i < 4; i++) {
        int row = crow + i * 16;
        CP_ASYNC16(smb + (uint32_t)(row * 144 + cu * 16),
                   Kg + (size_t)row * DHEAD + cu * 8);
        CP_ASYNC16(smb + (uint32_t)(64 * 144 + row * 144 + cu * 16),
                   VTg + (size_t)row * T_SEQ + cu * 8);
    }
    CP_COMMIT();

    // stage Q (64x64) through stage-1 region, hoist to registers
    {
        __half* Qst = smh + ATT_STAGE_H;
        const __half* Qp = g_Q + ((size_t)rh * T_SEQ + qbase) * DHEAD;
        #pragma unroll
        for (int i = 0; i < 4; i++) {
            int row = crow + i * 16;
            *(uint4*)&Qst[row * STRH + cu * 8] =
                *(const uint4*)&Qp[(size_t)row * DHEAD + cu * 8];
        }
    }
    __syncthreads();

    uint32_t qf[4][4];
    {
        const __half* Qst = smh + ATT_STAGE_H;
        #pragma unroll
        for (int ks = 0; ks < 4; ks++) {
            int k0 = ks * 16;
            qf[ks][0] = *(const uint32_t*)&Qst[(wrow + g) * STRH + k0 + qk2];
            qf[ks][1] = *(const uint32_t*)&Qst[(wrow + 8 + g) * STRH + k0 + qk2];
            qf[ks][2] = *(const uint32_t*)&Qst[(wrow + g) * STRH + k0 + 8 + qk2];
            qf[ks][3] = *(const uint32_t*)&Qst[(wrow + 8 + g) * STRH + k0 + 8 + qk2];
        }
    }

    float o[8][4] = {};
    float m0r = -1e30f, m1r = -1e30f;
    float lp0 = 0.f, lp1 = 0.f;

    // ======================= main loop: full tiles, no masks ==============
    for (int kt = 0; kt < qt; kt++) {
        CP_WAIT0();
        __syncthreads();

        {   // prefetch tile kt+1 (always exists)
            uint32_t sb = smb + (uint32_t)(((kt + 1) & 1) * ATT_STAGE_H) * 2;
            int kb = (kt + 1) * 64;
            #pragma unroll
            for (int i = 0; i < 4; i++) {
                int row = crow + i * 16;
                CP_ASYNC16(sb + (uint32_t)(row * 144 + cu * 16),
                           Kg + (size_t)(kb + row) * DHEAD + cu * 8);
                CP_ASYNC16(sb + (uint32_t)(64 * 144 + row * 144 + cu * 16),
                           VTg + (size_t)row * T_SEQ + kb + cu * 8);
            }
            CP_COMMIT();
        }

        const __half* Ks = smh + (kt & 1) * ATT_STAGE_H;
        const __half* Vs = Ks + 64 * STRH;

        // ---- S = Q K^T ----
        float s[8][4] = {};
        #pragma unroll
        for (int ks = 0; ks < 4; ks++) {
            int k0 = ks * 16;
            #pragma unroll
            for (int nt = 0; nt < 8; nt++) {
                uint32_t bf[2];
                bf[0] = *(const uint32_t*)&Ks[(nt * 8 + g) * STRH + k0 + qk2];
                bf[1] = *(const uint32_t*)&Ks[(nt * 8 + g) * STRH + k0 + 8 + qk2];
                mma_f16(s[nt], qf[ks], bf);
            }
        }

        // ---- online softmax (exp2 domain, deferred l) ----
        float tmax0 = -1e30f, tmax1 = -1e30f;
        #pragma unroll
        for (int nt = 0; nt < 8; nt++) {
            tmax0 = fmaxf(tmax0, fmaxf(s[nt][0], s[nt][1]));
            tmax1 = fmaxf(tmax1, fmaxf(s[nt][2], s[nt][3]));
        }
        tmax0 = fmaxf(tmax0, __shfl_xor_sync(0xffffffffu, tmax0, 1));
        tmax0 = fmaxf(tmax0, __shfl_xor_sync(0xffffffffu, tmax0, 2));
        tmax1 = fmaxf(tmax1, __shfl_xor_sync(0xffffffffu, tmax1, 1));
        tmax1 = fmaxf(tmax1, __shfl_xor_sync(0xffffffffu, tmax1, 2));

        float nm0 = fmaxf(m0r, tmax0), nm1 = fmaxf(m1r, tmax1);
        float scl0 = exp2f(m0r - nm0), scl1 = exp2f(m1r - nm1);
        float ts0 = 0.f, ts1 = 0.f;
        #pragma unroll
        for (int nt = 0; nt < 8; nt++) {
            s[nt][0] = exp2f(s[nt][0] - nm0);
            s[nt][1] = exp2f(s[nt][1] - nm0);
            s[nt][2] = exp2f(s[nt][2] - nm1);
            s[nt][3] = exp2f(s[nt][3] - nm1);
            ts0 += s[nt][0] + s[nt][1];
            ts1 += s[nt][2] + s[nt][3];
        }
        lp0 = lp0 * scl0 + ts0;
        lp1 = lp1 * scl1 + ts1;
        m0r = nm0; m1r = nm1;
        #pragma unroll
        for (int nt = 0; nt < 8; nt++) {
            o[nt][0] *= scl0; o[nt][1] *= scl0;
            o[nt][2] *= scl1; o[nt][3] *= scl1;
        }

        // ---- O += P @ V  (P packs directly into fp16 A fragments) ----
        #pragma unroll
        for (int j = 0; j < 4; j++) {
            uint32_t af[4];
            af[0] = pack_h2(s[2 * j][0], s[2 * j][1]);
            af[1] = pack_h2(s[2 * j][2], s[2 * j][3]);
            af[2] = pack_h2(s[2 * j + 1][0], s[2 * j + 1][1]);
            af[3] = pack_h2(s[2 * j + 1][2], s[2 * j + 1][3]);
            int k0 = j * 16;
            #pragma unroll
            for (int ot = 0; ot < 8; ot++) {
                uint32_t bf[2];
                bf[0] = *(const uint32_t*)&Vs[(ot * 8 + g) * STRH + k0 + qk2];
                bf[1] = *(const uint32_t*)&Vs[(ot * 8 + g) * STRH + k0 + 8 + qk2];
                mma_f16(o[ot], af, bf);
            }
        }
    }

    // ======================= diagonal tile (kt = qt) ======================
    {
        CP_WAIT0();
        __syncthreads();

        const __half* Ks = smh + (qt & 1) * ATT_STAGE_H;
        const __half* Vs = Ks + 64 * STRH;
        const int ntmax = 2 * warp + 1;

        float s[8][4] = {};
        #pragma unroll
        for (int ks = 0; ks < 4; ks++) {
            int k0 = ks * 16;
            #pragma unroll
            for (int nt = 0; nt < 8; nt++) {
                if (nt <= ntmax) {
                    uint32_t bf[2];
                    bf[0] = *(const uint32_t*)&Ks[(nt * 8 + g) * STRH + k0 + qk2];
                    bf[1] = *(const uint32_t*)&Ks[(nt * 8 + g) * STRH + k0 + 8 + qk2];
                    mma_f16(s[nt], qf[ks], bf);
                }
            }
        }

        const int row0 = qbase + wrow + g;
        const int row1 = row0 + 8;

        #pragma unroll
        for (int nt = 0; nt < 8; nt++) {
            if (nt <= ntmax) {
                int c0 = qbase + nt * 8 + qk2;
                if (c0 > row0)     s[nt][0] = -1e30f;
                if (c0 + 1 > row0) s[nt][1] = -1e30f;
                if (c0 > row1)     s[nt][2] = -1e30f;
                if (c0 + 1 > row1) s[nt][3] = -1e30f;
            }
        }

        float tmax0 = -1e30f, tmax1 = -1e30f;
        #pragma unroll
        for (int nt = 0; nt < 8; nt++) {
            if (nt <= ntmax) {
                tmax0 = fmaxf(tmax0, fmaxf(s[nt][0], s[nt][1]));
                tmax1 = fmaxf(tmax1, fmaxf(s[nt][2], s[nt][3]));
            }
        }
        tmax0 = fmaxf(tmax0, __shfl_xor_sync(0xffffffffu, tmax0, 1));
        tmax0 = fmaxf(tmax0, __shfl_xor_sync(0xffffffffu, tmax0, 2));
        tmax1 = fmaxf(tmax1, __shfl_xor_sync(0xffffffffu, tmax1, 1));
        tmax1 = fmaxf(tmax1, __shfl_xor_sync(0xffffffffu, tmax1, 2));

        float nm0 = fmaxf(m0r, tmax0), nm1 = fmaxf(m1r, tmax1);
        float scl0 = exp2f(m0r - nm0), scl1 = exp2f(m1r - nm1);
        float ts0 = 0.f, ts1 = 0.f;
        #pragma unroll
        for (int nt = 0; nt < 8; nt++) {
            if (nt <= ntmax) {
                s[nt][0] = exp2f(s[nt][0] - nm0);
                s[nt][1] = exp2f(s[nt][1] - nm0);
                s[nt][2] = exp2f(s[nt][2] - nm1);
                s[nt][3] = exp2f(s[nt][3] - nm1);
                ts0 += s[nt][0] + s[nt][1];
                ts1 += s[nt][2] + s[nt][3];
            }
        }
        lp0 = lp0 * scl0 + ts0;
        lp1 = lp1 * scl1 + ts1;
        #pragma unroll
        for (int nt = 0; nt < 8; nt++) {
            o[nt][0] *= scl0; o[nt][1] *= scl0;
            o[nt][2] *= scl1; o[nt][3] *= scl1;
        }

        #pragma unroll
        for (int j = 0; j < 4; j++) {
            if (2 * j <= ntmax) {
                uint32_t af[4];
                af[0] = pack_h2(s[2 * j][0], s[2 * j][1]);
                af[1] = pack_h2(s[2 * j][2], s[2 * j][3]);
                af[2] = pack_h2(s[2 * j + 1][0], s[2 * j + 1][1]);
                af[3] = pack_h2(s[2 * j + 1][2], s[2 * j + 1][3]);
                int k0 = j * 16;
                #pragma unroll
                for (int ot = 0; ot < 8; ot++) {
                    uint32_t bf[2];
                    bf[0] = *(const uint32_t*)&Vs[(ot * 8 + g) * STRH + k0 + qk2];
                    bf[1] = *(const uint32_t*)&Vs[(ot * 8 + g) * STRH + k0 + 8 + qk2];
                    mma_f16(o[ot], af, bf);
                }
            }
        }
    }

    // ---- final l reduction across the quad ----
    float l0 = lp0, l1 = lp1;
    l0 += __shfl_xor_sync(0xffffffffu, l0, 1);
    l0 += __shfl_xor_sync(0xffffffffu, l0, 2);
    l1 += __shfl_xor_sync(0xffffffffu, l1, 1);
    l1 += __shfl_xor_sync(0xffffffffu, l1, 2);

    // ---- epilogue: normalize, pad mask, residual, fp16 store ----
    const bool valid = (pad_mask[r] != 0);
    const float inv0 = 1.0f / l0, inv1 = 1.0f / l1;
    const int t0 = qbase + wrow + g;
    const int t1 = t0 + 8;
    #pragma unroll
    for (int nt = 0; nt < 8; nt++) {
        int dh = nt * 8 + qk2;
        size_t xoff0 = ((size_t)r * T_SEQ + t0) * D_MOD + h * DHEAD + dh;
        size_t yoff0 = ((size_t)t0 * N_NEU + r) * D_MOD + h * DHEAD + dh;
        __half2 rx0 = *(const __half2*)&g_XNh[xoff0];
        float2 rf0 = __half22float2(rx0);
        float ox0 = (valid ? o[nt][0] * inv0 : 0.f) + rf0.x;
        float oy0 = (valid ? o[nt][1] * inv0 : 0.f) + rf0.y;
        *(uint32_t*)&g_Yt[yoff0] = pack_h2(ox0, oy0);

        size_t xoff1 = ((size_t)r * T_SEQ + t1) * D_MOD + h * DHEAD + dh;
        size_t yoff1 = ((size_t)t1 * N_NEU + r) * D_MOD + h * DHEAD + dh;
        __half2 rx1 = *(const __half2*)&g_XNh[xoff1];
        float2 rf1 = __half22float2(rx1);
        float ox1 = (valid ? o[nt][2] * inv1 : 0.f) + rf1.x;
        float oy1 = (valid ? o[nt][3] * inv1 : 0.f) + rf1.y;
        *(uint32_t*)&g_Yt[yoff1] = pack_h2(ox1, oy1);
    }
}

// ---------------------------------------------------------------------------
// Kernel 4: output projection (fp16 TC), fp32 output.
// ---------------------------------------------------------------------------
__global__ void __launch_bounds__(128, 3)
out_gemm_tc_kernel(float* __restrict__ out) {
    extern __shared__ __half dynsm_h[];

    int n0 = blockIdx.x * 128;
    int m0 = blockIdx.y * 128;
    int tid = threadIdx.x;

    float c[4][8][4] = {};
    gemm_mainloop_f16(g_Yt, g_Wh + (size_t)3 * WSZ, m0, n0, dynsm_h, c, tid);

    const int lane = tid & 31;
    const int warp = tid >> 5;
    const int wm = warp & 1, wn = warp >> 1;
    const int g = lane >> 2, qk = lane & 3;

    #pragma unroll
    for (int mt = 0; mt < 4; mt++) {
        #pragma unroll
        for (int half_i = 0; half_i < 2; half_i++) {
            int m = m0 + wm * 64 + mt * 16 + g + half_i * 8;
            #pragma unroll
            for (int nt = 0; nt < 8; nt++) {
                int col = n0 + wn * 64 + nt * 8 + qk * 2;
                float2 v;
                v.x = c[mt][nt][half_i * 2 + 0];
                v.y = c[mt][nt][half_i * 2 + 1];
                *(float2*)(out + (size_t)m * 512 + col) = v;
            }
        }
    }
}

// ---------------------------------------------------------------------------
extern "C" void kernel_launch(void* const* d_in, const int* in_sizes, int n_in,
                              void* d_out, int out_size) {
    const float* x       = (const float*)d_in[0];
    const int*   pad     = (const int*)d_in[1];
    const float* norm_w  = (const float*)d_in[2];
    const float* wq      = (const float*)d_in[3];
    const float* wk      = (const float*)d_in[4];
    const float* wv      = (const float*)d_in[5];
    const float* wo      = (const float*)d_in[6];
    float* out = (float*)d_out;
    (void)in_sizes; (void)n_in; (void)out_size;

    cudaFuncSetAttribute(attn_tc_kernel,
                         cudaFuncAttributeMaxDynamicSharedMemorySize,
                         ATT_SMEM_BYTES);
    cudaFuncSetAttribute(qkv_gemm_tc_kernel,
                         cudaFuncAttributeMaxDynamicSharedMemorySize,
                         GEMM_SMEM_BYTES);
    cudaFuncSetAttribute(out_gemm_tc_kernel,
                         cudaFuncAttributeMaxDynamicSharedMemorySize,
                         GEMM_SMEM_BYTES);

    // 1. RMSNorm + transpose (fp16) fused with weights -> fp16
    rmsnorm_wcvt_kernel<<<M_ROWS + 4 * WSZ / 256, 128>>>(x, norm_w,
                                                         wq, wk, wv, wo);

    // 2. QKV projection (fp16 TC) + fused RoPE; V stored transposed
    qkv_gemm_tc_kernel<<<dim3(1536 / 128, M_ROWS / 128), 128,
                         GEMM_SMEM_BYTES>>>();

    // 3. fp16 tensor-core causal attention (4 CTAs/SM)
    attn_tc_kernel<<<dim3(T_SEQ / 64, N_NEU * H_HEADS), 128,
                     ATT_SMEM_BYTES>>>(pad);

    // 4. output projection (fp16 TC)
    out_gemm_tc_kernel<<<dim3(512 / 128, M_ROWS / 128), 128,
                         GEMM_SMEM_BYTES>>>(out);
}

// round 17
// speedup vs baseline: 2.3284x; 1.0789x over previous
#include <cuda_runtime.h>
#include <cuda_fp16.h>
#include <math.h>
#include <stdint.h>

// Problem constants
#define T_SEQ 384
#define N_NEU 128
#define D_MOD 512
#define H_HEADS 8
#define DHEAD 64
#define M_ROWS (N_NEU * T_SEQ)   // 49152
#define QKV_ELEMS (N_NEU * H_HEADS * T_SEQ * DHEAD)  // 25165824
#define WSZ (D_MOD * D_MOD)      // 262144

// Q pre-scale: (1/sqrt(64)) * log2(e) so softmax can use raw exp2
#define QSCALE 0.18033688011112042f

// Scratch (device globals) — fp16 storage everywhere
__device__ __half g_XNh[N_NEU * T_SEQ * D_MOD];   // rmsnormed x (also residual)
__device__ __half g_Q[QKV_ELEMS];                 // (rh, t, dh), rope+scale
__device__ __half g_K[QKV_ELEMS];                 // (rh, t, dh), rope
__device__ __half g_VT[QKV_ELEMS];                // (rh, dh, t)  TRANSPOSED
__device__ __half g_Yt[M_ROWS * D_MOD];           // (t*128+n, d)
__device__ __half g_Wh[4 * WSZ];                  // weights: wq,wk,wv,wo

// ---------------------------------------------------------------------------
// helpers
// ---------------------------------------------------------------------------
__device__ __forceinline__ uint32_t pack_h2(float x, float y) {
    __half2 h = __floats2half2_rn(x, y);   // x -> low half
    return *(uint32_t*)&h;
}

__device__ __forceinline__ void mma_f16(float c[4], const uint32_t a[4],
                                        const uint32_t b0, const uint32_t b1) {
    asm volatile(
        "mma.sync.aligned.m16n8k16.row.col.f32.f16.f16.f32 "
        "{%0,%1,%2,%3}, {%4,%5,%6,%7}, {%8,%9}, {%0,%1,%2,%3};"
        : "+f"(c[0]), "+f"(c[1]), "+f"(c[2]), "+f"(c[3])
        : "r"(a[0]), "r"(a[1]), "r"(a[2]), "r"(a[3]),
          "r"(b0), "r"(b1));
}

__device__ __forceinline__ uint32_t smem_u32(const void* p) {
    return (uint32_t)__cvta_generic_to_shared(p);
}
__device__ __forceinline__ void ldmx4(uint32_t r[4], uint32_t addr) {
    asm volatile(
        "ldmatrix.sync.aligned.m8n8.x4.shared.b16 {%0,%1,%2,%3}, [%4];"
        : "=r"(r[0]), "=r"(r[1]), "=r"(r[2]), "=r"(r[3]) : "r"(addr));
}
#define CP_ASYNC16(dst, src) \
    asm volatile("cp.async.cg.shared.global [%0], [%1], 16;" \
                 :: "r"(dst), "l"(src))
#define CP_COMMIT() asm volatile("cp.async.commit_group;" ::: "memory")
#define CP_WAIT0()  asm volatile("cp.async.wait_group 0;" ::: "memory")

// ---------------------------------------------------------------------------
// Kernel 1: RMSNorm + transpose fused with weight->fp16 conversion.
// ---------------------------------------------------------------------------
__global__ void rmsnorm_wcvt_kernel(const float* __restrict__ x,
                                    const float* __restrict__ w,
                                    const float* __restrict__ wq,
                                    const float* __restrict__ wk,
                                    const float* __restrict__ wv,
                                    const float* __restrict__ wo) {
    if (blockIdx.x >= M_ROWS) {
        int i = ((blockIdx.x - M_ROWS) * 128 + threadIdx.x) * 2;
        int wsel = i >> 18;
        int j = i & (WSZ - 1);
        const float* src = (wsel == 0) ? wq : (wsel == 1) ? wk
                          : (wsel == 2) ? wv : wo;
        *(uint32_t*)&g_Wh[i] = pack_h2(src[j], src[j + 1]);
        return;
    }

    int row = blockIdx.x;          // row = t*128 + n
    int t = row >> 7;
    int n = row & 127;
    int tid = threadIdx.x;

    float4 v = ((const float4*)(x + (size_t)row * D_MOD))[tid];
    float ss = v.x * v.x + v.y * v.y + v.z * v.z + v.w * v.w;
    #pragma unroll
    for (int m = 16; m; m >>= 1) ss += __shfl_xor_sync(0xffffffffu, ss, m);

    __shared__ float sbuf[4];
    if ((tid & 31) == 0) sbuf[tid >> 5] = ss;
    __syncthreads();
    float tot = sbuf[0] + sbuf[1] + sbuf[2] + sbuf[3];
    float inv = rsqrtf(tot * (1.0f / (float)D_MOD) + 1e-6f);

    float4 wvec = ((const float4*)w)[tid];
    uint2 ot;
    ot.x = pack_h2(v.x * inv * wvec.x, v.y * inv * wvec.y);
    ot.y = pack_h2(v.z * inv * wvec.z, v.w * inv * wvec.w);
    *(uint2*)&g_XNh[((size_t)n * T_SEQ + t) * D_MOD + 4 * tid] = ot;
}

// ---------------------------------------------------------------------------
// GEMM mainloop: C(128x128) = A(128xK) * B(128xK)^T, K=512, fp16/fp32 acc.
// 128 threads, warp tile 64x64, mma m16n8k16, ldmatrix fragment loads.
// K-chunk 64 halfs, 2-stage cp.async. smem 73728 B -> 3 CTAs/SM.
// ---------------------------------------------------------------------------
#define STRH 72
#define GEMM_STAGE_H (2 * 128 * STRH)
#define GEMM_SMEM_BYTES (2 * GEMM_STAGE_H * 2)  // 73728 B

__device__ __forceinline__ void gemm_mainloop_f16(
    const __half* __restrict__ A, const __half* __restrict__ B,
    int m0, int n0row, __half* __restrict__ sm,
    float c[4][8][4], int tid)
{
    const int lane = tid & 31;
    const int warp = tid >> 5;
    const int wm = warp & 1;
    const int wn = warp >> 1;

    // ldmatrix addressing lanes
    const int a_r = wm * 64 + (lane & 15);          // A tile row
    const int a_c = (lane >> 4) << 3;               // A tile col offset
    const int b_r = wn * 64 + ((lane >> 4) << 3) + (lane & 7);
    const int b_c = ((lane >> 3) & 1) << 3;

    const uint32_t smb = smem_u32(sm);
    const int crow = tid >> 3;          // 0..15 (+16*i)
    const int cu = tid & 7;

    // prologue: chunk 0 -> stage 0
    #pragma unroll
    for (int i = 0; i < 8; i++) {
        int row = crow + i * 16;
        CP_ASYNC16(smb + (uint32_t)(row * 144 + cu * 16),
                   A + (size_t)(m0 + row) * 512 + cu * 8);
        CP_ASYNC16(smb + (uint32_t)(128 * 144 + row * 144 + cu * 16),
                   B + (size_t)(n0row + row) * 512 + cu * 8);
    }
    CP_COMMIT();

    for (int kb = 0; kb < 8; kb++) {
        CP_WAIT0();
        __syncthreads();

        const uint32_t As = smb + (uint32_t)((kb & 1) * GEMM_STAGE_H) * 2;
        const uint32_t Bs = As + 128 * 144;

        if (kb + 1 < 8) {
            uint32_t st = smb + (uint32_t)(((kb + 1) & 1) * GEMM_STAGE_H) * 2;
            int kc = (kb + 1) * 64;
            #pragma unroll
            for (int i = 0; i < 8; i++) {
                int row = crow + i * 16;
                CP_ASYNC16(st + (uint32_t)(row * 144 + cu * 16),
                           A + (size_t)(m0 + row) * 512 + kc + cu * 8);
                CP_ASYNC16(st + (uint32_t)(128 * 144 + row * 144 + cu * 16),
                           B + (size_t)(n0row + row) * 512 + kc + cu * 8);
            }
            CP_COMMIT();
        }

        #pragma unroll
        for (int ks = 0; ks < 4; ks++) {
            int k0 = ks * 16;
            uint32_t af[4][4];
            #pragma unroll
            for (int mt = 0; mt < 4; mt++)
                ldmx4(af[mt], As + (uint32_t)(((a_r + mt * 16) * STRH + k0 + a_c) * 2));
            #pragma unroll
            for (int p = 0; p < 4; p++) {
                uint32_t bq[4];
                ldmx4(bq, Bs + (uint32_t)(((b_r + p * 16) * STRH + k0 + b_c) * 2));
                #pragma unroll
                for (int mt = 0; mt < 4; mt++) {
                    mma_f16(c[mt][2 * p],     af[mt], bq[0], bq[1]);
                    mma_f16(c[mt][2 * p + 1], af[mt], bq[2], bq[3]);
                }
            }
        }
    }
}

// ---------------------------------------------------------------------------
// Kernel 2: QKV projection (fp16 TC) + fused RoPE / q-scale.
// Q/K written (rh,t,dh); V written TRANSPOSED (rh,dh,t).
// ---------------------------------------------------------------------------
__global__ void __launch_bounds__(128, 3)
qkv_gemm_tc_kernel() {
    extern __shared__ __half dynsm_h[];

    int n0 = blockIdx.x * 128;
    int m0 = blockIdx.y * 128;
    int which = n0 >> 9;                 // 0=Q, 1=K, 2=V
    int cc0 = n0 & 511;

    int tid = threadIdx.x;
    float c[4][8][4] = {};
    gemm_mainloop_f16(g_XNh, g_Wh + (size_t)which * WSZ, m0, cc0, dynsm_h, c, tid);

    const int lane = tid & 31;
    const int warp = tid >> 5;
    const int wm = warp & 1, wn = warp >> 1;
    const int g = lane >> 2, qk = lane & 3;

    #pragma unroll
    for (int mt = 0; mt < 4; mt++) {
        #pragma unroll
        for (int half_i = 0; half_i < 2; half_i++) {
            int m = m0 + wm * 64 + mt * 16 + g + half_i * 8;
            int r = m / T_SEQ;
            int t = m - r * T_SEQ;
            #pragma unroll
            for (int nt = 0; nt < 8; nt++) {
                int col = wn * 64 + nt * 8 + qk * 2;
                int cc = cc0 + col;
                int h = cc >> 6, dh = cc & 63;
                float vx = c[mt][nt][half_i * 2 + 0];
                float vy = c[mt][nt][half_i * 2 + 1];
                if (which <= 1 && dh < 32) {
                    int i = dh >> 1;
                    float invf = __expf(-(float)i * 0.57564627324851142f);
                    float sn, cs;
                    sincosf((float)t * invf, &sn, &cs);
                    float a = vx, b = vy;
                    vx = a * cs - b * sn;
                    vy = a * sn + b * cs;
                }
                size_t rh = (size_t)(r * H_HEADS + h);
                if (which == 0) {
                    vx *= QSCALE; vy *= QSCALE;
                    *(uint32_t*)&g_Q[(rh * T_SEQ + t) * DHEAD + dh] = pack_h2(vx, vy);
                } else if (which == 1) {
                    *(uint32_t*)&g_K[(rh * T_SEQ + t) * DHEAD + dh] = pack_h2(vx, vy);
                } else {
                    g_VT[(rh * DHEAD + dh) * T_SEQ + t]     = __float2half_rn(vx);
                    g_VT[(rh * DHEAD + dh + 1) * T_SEQ + t] = __float2half_rn(vy);
                }
            }
        }
    }
}

// ---------------------------------------------------------------------------
// Kernel 3: fp16 tensor-core causal flash attention, ldmatrix fragments.
// q-tile 64, 128 threads, 4 CTAs/SM. 2-stage cp.async KV ring (K + V^T);
// Softmax exp2-domain, deferred l. P packed to fp16 A-frags directly.
// Diagonal tile split with warp-uniform pair bound (p <= warp).
// ---------------------------------------------------------------------------
#define ATT_STAGE_H (2 * 64 * STRH)              // 9216 halfs per stage (K+VT)
#define ATT_SMEM_BYTES (2 * ATT_STAGE_H * 2)     // 36864 B

__global__ void __launch_bounds__(128, 4)
attn_tc_kernel(const int* __restrict__ pad_mask) {
    extern __shared__ __half smh[];

    const int qt = blockIdx.x;           // 0..5
    const int rh = blockIdx.y;
    const int r = rh >> 3, h = rh & 7;
    const int qbase = qt * 64;

    const int tid = threadIdx.x;
    const int warp = tid >> 5;           // 0..3
    const int lane = tid & 31;
    const int g = lane >> 2;
    const int qk = lane & 3;
    const int qk2 = qk * 2;
    const int wrow = warp * 16;

    // ldmatrix lanes (A pattern for Q; B pattern for K/V)
    const int a_rl = (lane & 15);
    const int a_c = (lane >> 4) << 3;
    const int b_r = ((lane >> 4) << 3) + (lane & 7);
    const int b_c = ((lane >> 3) & 1) << 3;

    const uint32_t smb = smem_u32(smh);
    const int crow = tid >> 3;           // 0..15 (+16*i)
    const int cu = tid & 7;

    const __half* Kg = g_K + (size_t)rh * T_SEQ * DHEAD;
    const __half* VTg = g_VT + (size_t)rh * DHEAD * T_SEQ;

    // prologue: kv tile 0 -> stage 0 (K rows kv x d; VT rows dh x t)
    #pragma unroll
    for (int i = 0; i < 4; i++) {
        int row = crow + i * 16;
        CP_ASYNC16(smb + (uint32_t)(row * 144 + cu * 16),
                   Kg + (size_t)row * DHEAD + cu * 8);
        CP_ASYNC16(smb + (uint32_t)(64 * 144 + row * 144 + cu * 16),
                   VTg + (size_t)row * T_SEQ + cu * 8);
    }
    CP_COMMIT();

    // stage Q (64x64) through stage-1 region, hoist to registers via ldmatrix
    {
        __half* Qst = smh + ATT_STAGE_H;
        const __half* Qp = g_Q + ((size_t)rh * T_SEQ + qbase) * DHEAD;
        #pragma unroll
        for (int i = 0; i < 4; i++) {
            int row = crow + i * 16;
            *(uint4*)&Qst[row * STRH + cu * 8] =
                *(const uint4*)&Qp[(size_t)row * DHEAD + cu * 8];
        }
    }
    __syncthreads();

    uint32_t qf[4][4];
    {
        const uint32_t Qst = smb + (uint32_t)ATT_STAGE_H * 2;
        #pragma unroll
        for (int ks = 0; ks < 4; ks++)
            ldmx4(qf[ks], Qst + (uint32_t)(((wrow + a_rl) * STRH + ks * 16 + a_c) * 2));
    }

    float o[8][4] = {};
    float m0r = -1e30f, m1r = -1e30f;
    float lp0 = 0.f, lp1 = 0.f;

    // ======================= main loop: full tiles, no masks ==============
    for (int kt = 0; kt < qt; kt++) {
        CP_WAIT0();
        __syncthreads();

        {   // prefetch tile kt+1 (always exists)
            uint32_t sb = smb + (uint32_t)(((kt + 1) & 1) * ATT_STAGE_H) * 2;
            int kb = (kt + 1) * 64;
            #pragma unroll
            for (int i = 0; i < 4; i++) {
                int row = crow + i * 16;
                CP_ASYNC16(sb + (uint32_t)(row * 144 + cu * 16),
                           Kg + (size_t)(kb + row) * DHEAD + cu * 8);
                CP_ASYNC16(sb + (uint32_t)(64 * 144 + row * 144 + cu * 16),
                           VTg + (size_t)row * T_SEQ + kb + cu * 8);
            }
            CP_COMMIT();
        }

        const uint32_t Ks = smb + (uint32_t)((kt & 1) * ATT_STAGE_H) * 2;
        const uint32_t Vs = Ks + 64 * 144;

        // ---- S = Q K^T ----
        float s[8][4] = {};
        #pragma unroll
        for (int ks = 0; ks < 4; ks++) {
            int k0 = ks * 16;
            #pragma unroll
            for (int p = 0; p < 4; p++) {
                uint32_t bq[4];
                ldmx4(bq, Ks + (uint32_t)(((b_r + p * 16) * STRH + k0 + b_c) * 2));
                mma_f16(s[2 * p],     qf[ks], bq[0], bq[1]);
                mma_f16(s[2 * p + 1], qf[ks], bq[2], bq[3]);
            }
        }

        // ---- online softmax (exp2 domain, deferred l) ----
        float tmax0 = -1e30f, tmax1 = -1e30f;
        #pragma unroll
        for (int nt = 0; nt < 8; nt++) {
            tmax0 = fmaxf(tmax0, fmaxf(s[nt][0], s[nt][1]));
            tmax1 = fmaxf(tmax1, fmaxf(s[nt][2], s[nt][3]));
        }
        tmax0 = fmaxf(tmax0, __shfl_xor_sync(0xffffffffu, tmax0, 1));
        tmax0 = fmaxf(tmax0, __shfl_xor_sync(0xffffffffu, tmax0, 2));
        tmax1 = fmaxf(tmax1, __shfl_xor_sync(0xffffffffu, tmax1, 1));
        tmax1 = fmaxf(tmax1, __shfl_xor_sync(0xffffffffu, tmax1, 2));

        float nm0 = fmaxf(m0r, tmax0), nm1 = fmaxf(m1r, tmax1);
        float scl0 = exp2f(m0r - nm0), scl1 = exp2f(m1r - nm1);
        float ts0 = 0.f, ts1 = 0.f;
        #pragma unroll
        for (int nt = 0; nt < 8; nt++) {
            s[nt][0] = exp2f(s[nt][0] - nm0);
            s[nt][1] = exp2f(s[nt][1] - nm0);
            s[nt][2] = exp2f(s[nt][2] - nm1);
            s[nt][3] = exp2f(s[nt][3] - nm1);
            ts0 += s[nt][0] + s[nt][1];
            ts1 += s[nt][2] + s[nt][3];
        }
        lp0 = lp0 * scl0 + ts0;
        lp1 = lp1 * scl1 + ts1;
        m0r = nm0; m1r = nm1;
        #pragma unroll
        for (int nt = 0; nt < 8; nt++) {
            o[nt][0] *= scl0; o[nt][1] *= scl0;
            o[nt][2] *= scl1; o[nt][3] *= scl1;
        }

        // ---- O += P @ V  (P packs directly into fp16 A fragments) ----
        #pragma unroll
        for (int j = 0; j < 4; j++) {
            uint32_t af[4];
            af[0] = pack_h2(s[2 * j][0], s[2 * j][1]);
            af[1] = pack_h2(s[2 * j][2], s[2 * j][3]);
            af[2] = pack_h2(s[2 * j + 1][0], s[2 * j + 1][1]);
            af[3] = pack_h2(s[2 * j + 1][2], s[2 * j + 1][3]);
            int k0 = j * 16;
            #pragma unroll
            for (int p = 0; p < 4; p++) {
                uint32_t bq[4];
                ldmx4(bq, Vs + (uint32_t)(((b_r + p * 16) * STRH + k0 + b_c) * 2));
                mma_f16(o[2 * p],     af, bq[0], bq[1]);
                mma_f16(o[2 * p + 1], af, bq[2], bq[3]);
            }
        }
    }

    // ======================= diagonal tile (kt = qt) ======================
    {
        CP_WAIT0();
        __syncthreads();

        const uint32_t Ks = smb + (uint32_t)((qt & 1) * ATT_STAGE_H) * 2;
        const uint32_t Vs = Ks + 64 * 144;
        const int ntmax = 2 * warp + 1;      // pairs p <= warp active

        float s[8][4] = {};
        #pragma unroll
        for (int ks = 0; ks < 4; ks++) {
            int k0 = ks * 16;
            #pragma unroll
            for (int p = 0; p < 4; p++) {
                if (p <= warp) {
                    uint32_t bq[4];
                    ldmx4(bq, Ks + (uint32_t)(((b_r + p * 16) * STRH + k0 + b_c) * 2));
                    mma_f16(s[2 * p],     qf[ks], bq[0], bq[1]);
                    mma_f16(s[2 * p + 1], qf[ks], bq[2], bq[3]);
                }
            }
        }

        const int row0 = qbase + wrow + g;
        const int row1 = row0 + 8;

        #pragma unroll
        for (int nt = 0; nt < 8; nt++) {
            if (nt <= ntmax) {
                int c0 = qbase + nt * 8 + qk2;
                if (c0 > row0)     s[nt][0] = -1e30f;
                if (c0 + 1 > row0) s[nt][1] = -1e30f;
                if (c0 > row1)     s[nt][2] = -1e30f;
                if (c0 + 1 > row1) s[nt][3] = -1e30f;
            }
        }

        float tmax0 = -1e30f, tmax1 = -1e30f;
        #pragma unroll
        for (int nt = 0; nt < 8; nt++) {
            if (nt <= ntmax) {
                tmax0 = fmaxf(tmax0, fmaxf(s[nt][0], s[nt][1]));
                tmax1 = fmaxf(tmax1, fmaxf(s[nt][2], s[nt][3]));
            }
        }
        tmax0 = fmaxf(tmax0, __shfl_xor_sync(0xffffffffu, tmax0, 1));
        tmax0 = fmaxf(tmax0, __shfl_xor_sync(0xffffffffu, tmax0, 2));
        tmax1 = fmaxf(tmax1, __shfl_xor_sync(0xffffffffu, tmax1, 1));
        tmax1 = fmaxf(tmax1, __shfl_xor_sync(0xffffffffu, tmax1, 2));

        float nm0 = fmaxf(m0r, tmax0), nm1 = fmaxf(m1r, tmax1);
        float scl0 = exp2f(m0r - nm0), scl1 = exp2f(m1r - nm1);
        float ts0 = 0.f, ts1 = 0.f;
        #pragma unroll
        for (int nt = 0; nt < 8; nt++) {
            if (nt <= ntmax) {
                s[nt][0] = exp2f(s[nt][0] - nm0);
                s[nt][1] = exp2f(s[nt][1] - nm0);
                s[nt][2] = exp2f(s[nt][2] - nm1);
                s[nt][3] = exp2f(s[nt][3] - nm1);
                ts0 += s[nt][0] + s[nt][1];
                ts1 += s[nt][2] + s[nt][3];
            }
        }
        lp0 = lp0 * scl0 + ts0;
        lp1 = lp1 * scl1 + ts1;
        #pragma unroll
        for (int nt = 0; nt < 8; nt++) {
            o[nt][0] *= scl0; o[nt][1] *= scl0;
            o[nt][2] *= scl1; o[nt][3] *= scl1;
        }

        #pragma unroll
        for (int j = 0; j < 4; j++) {
            if (j <= warp) {
                uint32_t af[4];
                af[0] = pack_h2(s[2 * j][0], s[2 * j][1]);
                af[1] = pack_h2(s[2 * j][2], s[2 * j][3]);
                af[2] = pack_h2(s[2 * j + 1][0], s[2 * j + 1][1]);
                af[3] = pack_h2(s[2 * j + 1][2], s[2 * j + 1][3]);
                int k0 = j * 16;
                #pragma unroll
                for (int p = 0; p < 4; p++) {
                    uint32_t bq[4];
                    ldmx4(bq, Vs + (uint32_t)(((b_r + p * 16) * STRH + k0 + b_c) * 2));
                    mma_f16(o[2 * p],     af, bq[0], bq[1]);
                    mma_f16(o[2 * p + 1], af, bq[2], bq[3]);
                }
            }
        }
    }

    // ---- final l reduction across the quad ----
    float l0 = lp0, l1 = lp1;
    l0 += __shfl_xor_sync(0xffffffffu, l0, 1);
    l0 += __shfl_xor_sync(0xffffffffu, l0, 2);
    l1 += __shfl_xor_sync(0xffffffffu, l1, 1);
    l1 += __shfl_xor_sync(0xffffffffu, l1, 2);

    // ---- epilogue: normalize, pad mask, residual, fp16 store ----
    const bool valid = (pad_mask[r] != 0);
    const float inv0 = 1.0f / l0, inv1 = 1.0f / l1;
    const int t0 = qbase + wrow + g;
    const int t1 = t0 + 8;
    #pragma unroll
    for (int nt = 0; nt < 8; nt++) {
        int dh = nt * 8 + qk2;
        size_t xoff0 = ((size_t)r * T_SEQ + t0) * D_MOD + h * DHEAD + dh;
        size_t yoff0 = ((size_t)t0 * N_NEU + r) * D_MOD + h * DHEAD + dh;
        __half2 rx0 = *(const __half2*)&g_XNh[xoff0];
        float2 rf0 = __half22float2(rx0);
        float ox0 = (valid ? o[nt][0] * inv0 : 0.f) + rf0.x;
        float oy0 = (valid ? o[nt][1] * inv0 : 0.f) + rf0.y;
        *(uint32_t*)&g_Yt[yoff0] = pack_h2(ox0, oy0);

        size_t xoff1 = ((size_t)r * T_SEQ + t1) * D_MOD + h * DHEAD + dh;
        size_t yoff1 = ((size_t)t1 * N_NEU + r) * D_MOD + h * DHEAD + dh;
        __half2 rx1 = *(const __half2*)&g_XNh[xoff1];
        float2 rf1 = __half22float2(rx1);
        float ox1 = (valid ? o[nt][2] * inv1 : 0.f) + rf1.x;
        float oy1 = (valid ? o[nt][3] * inv1 : 0.f) + rf1.y;
        *(uint32_t*)&g_Yt[yoff1] = pack_h2(ox1, oy1);
    }
}

// ---------------------------------------------------------------------------
// Kernel 4: output projection (fp16 TC), fp32 output.
// ---------------------------------------------------------------------------
__global__ void __launch_bounds__(128, 3)
out_gemm_tc_kernel(float* __restrict__ out) {
    extern __shared__ __half dynsm_h[];

    int n0 = blockIdx.x * 128;
    int m0 = blockIdx.y * 128;
    int tid = threadIdx.x;

    float c[4][8][4] = {};
    gemm_mainloop_f16(g_Yt, g_Wh + (size_t)3 * WSZ, m0, n0, dynsm_h, c, tid);

    const int lane = tid & 31;
    const int warp = tid >> 5;
    const int wm = warp & 1, wn = warp >> 1;
    const int g = lane >> 2, qk = lane & 3;

    #pragma unroll
    for (int mt = 0; mt < 4; mt++) {
        #pragma unroll
        for (int half_i = 0; half_i < 2; half_i++) {
            int m = m0 + wm * 64 + mt * 16 + g + half_i * 8;
            #pragma unroll
            for (int nt = 0; nt < 8; nt++) {
                int col = n0 + wn * 64 + nt * 8 + qk * 2;
                float2 v;
                v.x = c[mt][nt][half_i * 2 + 0];
                v.y = c[mt][nt][half_i * 2 + 1];
                *(float2*)(out + (size_t)m * 512 + col) = v;
            }
        }
    }
}

// ---------------------------------------------------------------------------
extern "C" void kernel_launch(void* const* d_in, const int* in_sizes, int n_in,
                              void* d_out, int out_size) {
    const float* x       = (const float*)d_in[0];
    const int*   pad     = (const int*)d_in[1];
    const float* norm_w  = (const float*)d_in[2];
    const float* wq      = (const float*)d_in[3];
    const float* wk      = (const float*)d_in[4];
    const float* wv      = (const float*)d_in[5];
    const float* wo      = (const float*)d_in[6];
    float* out = (float*)d_out;
    (void)in_sizes; (void)n_in; (void)out_size;

    cudaFuncSetAttribute(attn_tc_kernel,
                         cudaFuncAttributeMaxDynamicSharedMemorySize,
                         ATT_SMEM_BYTES);
    cudaFuncSetAttribute(qkv_gemm_tc_kernel,
                         cudaFuncAttributeMaxDynamicSharedMemorySize,
                         GEMM_SMEM_BYTES);
    cudaFuncSetAttribute(out_gemm_tc_kernel,
                         cudaFuncAttributeMaxDynamicSharedMemorySize,
                         GEMM_SMEM_BYTES);

    // 1. RMSNorm + transpose (fp16) fused with weights -> fp16
    rmsnorm_wcvt_kernel<<<M_ROWS + 4 * WSZ / 256, 128>>>(x, norm_w,
                                                         wq, wk, wv, wo);

    // 2. QKV projection (fp16 TC, ldmatrix) + fused RoPE; V transposed
    qkv_gemm_tc_kernel<<<dim3(1536 / 128, M_ROWS / 128), 128,
                         GEMM_SMEM_BYTES>>>();

    // 3. fp16 tensor-core causal attention (ldmatrix, 4 CTAs/SM)
    attn_tc_kernel<<<dim3(T_SEQ / 64, N_NEU * H_HEADS), 128,
                     ATT_SMEM_BYTES>>>(pad);

    // 4. output projection (fp16 TC, ldmatrix)
    out_gemm_tc_kernel<<<dim3(512 / 128, M_ROWS / 128), 128,
                         GEMM_SMEM_BYTES>>>(out);
}